// round 3
// baseline (speedup 1.0000x reference)
#include <cuda_runtime.h>
#include <mma.h>
#include <math.h>

using namespace nvcuda;

#define Bc 2
#define Lc 2048
#define Dc 1024
#define Hc 16
#define DHc 64
#define NR (Bc*Lc)

// Scratch (device globals are the sanctioned no-alloc scratch mechanism)
__device__ float g_Q[NR*Dc];
__device__ float g_K[NR*Dc];
__device__ float g_V[NR*Dc];
__device__ float g_T[NR*Dc];

// ---------------------------------------------------------------------------
// Generic GEMM: C[M,N] = A[M,K] @ W[N,K]^T  (tf32 wmma, optional 3-term split)
// Block tile 128x128x32, 8 warps (4x2), each warp 32x64 (2x4 fragments).
// ---------------------------------------------------------------------------
template<bool SPLIT>
__global__ __launch_bounds__(256) void gemm_abt(
    const float* __restrict__ A, const float* __restrict__ W,
    float* __restrict__ C, int K, int lda, int ldb, int ldc)
{
    __shared__ float As[128*40];
    __shared__ float Bs[128*40];
    const int tid = threadIdx.x;
    const int m0 = blockIdx.y*128, n0 = blockIdx.x*128;
    const int wid = tid>>5;
    const int wm = wid>>1, wn = wid&1;

    wmma::fragment<wmma::accumulator,16,16,8,float> acc[2][4];
#pragma unroll
    for (int i=0;i<2;i++)
#pragma unroll
      for (int j=0;j<4;j++) wmma::fill_fragment(acc[i][j], 0.0f);

    for (int k0=0;k0<K;k0+=32) {
#pragma unroll
        for (int i=0;i<4;i++){
            int id = tid + i*256;
            int r = id>>3, c = (id&7)<<2;
            *(float4*)&As[r*40+c] = *(const float4*)&A[(size_t)(m0+r)*lda + k0 + c];
            *(float4*)&Bs[r*40+c] = *(const float4*)&W[(size_t)(n0+r)*ldb + k0 + c];
        }
        __syncthreads();
#pragma unroll
        for (int kk=0;kk<4;kk++){
            wmma::fragment<wmma::matrix_a,16,16,8,wmma::precision::tf32,wmma::row_major> ah[2], al[2];
            wmma::fragment<wmma::matrix_b,16,16,8,wmma::precision::tf32,wmma::col_major> bh[4], bl[4];
#pragma unroll
            for (int im=0;im<2;im++){
                wmma::load_matrix_sync(ah[im], &As[(wm*32+im*16)*40 + kk*8], 40);
#pragma unroll
                for (int t=0;t<ah[im].num_elements;t++){
                    float v = ah[im].x[t];
                    float hh = wmma::__float_to_tf32(v);
                    ah[im].x[t] = hh;
                    if (SPLIT) al[im].x[t] = wmma::__float_to_tf32(v - hh);
                }
            }
#pragma unroll
            for (int in=0;in<4;in++){
                wmma::load_matrix_sync(bh[in], &Bs[(wn*64+in*16)*40 + kk*8], 40);
#pragma unroll
                for (int t=0;t<bh[in].num_elements;t++){
                    float v = bh[in].x[t];
                    float hh = wmma::__float_to_tf32(v);
                    bh[in].x[t] = hh;
                    if (SPLIT) bl[in].x[t] = wmma::__float_to_tf32(v - hh);
                }
            }
#pragma unroll
            for (int im=0;im<2;im++)
#pragma unroll
              for (int in=0;in<4;in++){
                wmma::mma_sync(acc[im][in], ah[im], bh[in], acc[im][in]);
                if (SPLIT){
                    wmma::mma_sync(acc[im][in], ah[im], bl[in], acc[im][in]);
                    wmma::mma_sync(acc[im][in], al[im], bh[in], acc[im][in]);
                }
              }
        }
        __syncthreads();
    }
#pragma unroll
    for (int im=0;im<2;im++)
#pragma unroll
      for (int in=0;in<4;in++)
        wmma::store_matrix_sync(&C[(size_t)(m0+wm*32+im*16)*ldc + n0+wn*64+in*16],
                                acc[im][in], ldc, wmma::mem_row_major);
}

// ---------------------------------------------------------------------------
// xPos rotary + bias. One thread per (row, even-col pair). Also adds V bias.
// NOTE reference swaps: K comes from Wv/bv, V comes from Wk/bk (handled by
// which buffers/biases the host passes).
// ---------------------------------------------------------------------------
__global__ __launch_bounds__(256) void rope_bias_kernel(
    float* __restrict__ Q, float* __restrict__ K, float* __restrict__ V,
    const float* __restrict__ biasQ, const float* __restrict__ biasK,
    const float* __restrict__ biasV)
{
    int p = blockIdx.x*256 + threadIdx.x;     // p < NR*512
    int row = p >> 9;
    int col = (p & 511) << 1;                 // even column in [0,1024)
    int l = row & (Lc-1);
    int j = col & (DHc-1);                    // even dim within head
    float jf = (float)j;
    float inv_freq = powf(10000.0f, -jf * (1.0f/64.0f));
    float fr = (float)l * inv_freq;
    float sn, cs; sincosf(fr, &sn, &cs);
    float sv = (jf + 25.6f) * (1.0f/89.6f);
    float pw = ((float)l - 1024.0f) * (1.0f/512.0f);
    float sc = powf(sv, pw);
    float isc = 1.0f/sc;
    size_t base = (size_t)row*Dc + col;

    float q0 = Q[base] + biasQ[col], q1 = Q[base+1] + biasQ[col+1];
    Q[base]   = q0*cs*sc - q1*sn*sc;
    Q[base+1] = q1*cs*sc + q0*sn*sc;

    float k0 = K[base] + biasK[col], k1 = K[base+1] + biasK[col+1];
    K[base]   = k0*cs*isc - k1*sn*isc;
    K[base+1] = k1*cs*isc + k0*sn*isc;

    V[base]   += biasV[col];
    V[base+1] += biasV[col+1];
}

// ---------------------------------------------------------------------------
// Two-pass flash attention. CTA = (q-tile of 64 rows, one (b,h)). 4 warps.
// Pass A: stream K tiles, compute S=QK^T (split-tf32), track row max & sumexp.
// Pass B: recompute S, P = exp(S-m)/l, O += P@V (single tf32). No rescale.
// ---------------------------------------------------------------------------
#define TSZ (64*72)

__device__ __forceinline__ void qk_tile(
    const float* Qh, const float* Ql, const float* Kh, const float* Kl,
    float* Ss, int w)
{
    wmma::fragment<wmma::accumulator,16,16,8,float> sfr[4];
#pragma unroll
    for (int n=0;n<4;n++) wmma::fill_fragment(sfr[n], 0.0f);
#pragma unroll
    for (int kk=0;kk<8;kk++){
        wmma::fragment<wmma::matrix_a,16,16,8,wmma::precision::tf32,wmma::row_major> a_h, a_l;
        wmma::load_matrix_sync(a_h, &Qh[(w*16)*72 + kk*8], 72);
        wmma::load_matrix_sync(a_l, &Ql[(w*16)*72 + kk*8], 72);
#pragma unroll
        for (int t=0;t<a_h.num_elements;t++){
            a_h.x[t] = wmma::__float_to_tf32(a_h.x[t]);
            a_l.x[t] = wmma::__float_to_tf32(a_l.x[t]);
        }
#pragma unroll
        for (int n=0;n<4;n++){
            wmma::fragment<wmma::matrix_b,16,16,8,wmma::precision::tf32,wmma::col_major> b_h, b_l;
            wmma::load_matrix_sync(b_h, &Kh[(n*16)*72 + kk*8], 72);
            wmma::load_matrix_sync(b_l, &Kl[(n*16)*72 + kk*8], 72);
#pragma unroll
            for (int t=0;t<b_h.num_elements;t++){
                b_h.x[t] = wmma::__float_to_tf32(b_h.x[t]);
                b_l.x[t] = wmma::__float_to_tf32(b_l.x[t]);
            }
            wmma::mma_sync(sfr[n], a_h, b_h, sfr[n]);
            wmma::mma_sync(sfr[n], a_h, b_l, sfr[n]);
            wmma::mma_sync(sfr[n], a_l, b_h, sfr[n]);
        }
    }
#pragma unroll
    for (int n=0;n<4;n++)
        wmma::store_matrix_sync(&Ss[(w*16)*72 + n*16], sfr[n], 72, wmma::mem_row_major);
}

__global__ __launch_bounds__(128) void flash_kernel(
    const float* __restrict__ Q, const float* __restrict__ K,
    const float* __restrict__ V, float* __restrict__ O)
{
    extern __shared__ float sm[];
    float* Qh = sm;
    float* Ql = sm + 1*TSZ;
    float* Kh = sm + 2*TSZ;
    float* Kl = sm + 3*TSZ;
    float* Vs = sm + 4*TSZ;
    float* Ss = sm + 5*TSZ;
    const int tid = threadIdx.x;
    const int w = tid>>5, lane = tid&31;
    const int qt = blockIdx.x, bh = blockIdx.y;
    const int b = bh>>4, h = bh&15;
    const float* Qb = Q + ((size_t)b*Lc + qt*64)*Dc + h*64;
    const float* Kb = K + (size_t)b*Lc*Dc + h*64;
    const float* Vb = V + (size_t)b*Lc*Dc + h*64;

    // Load + pre-scale Q tile (1/sqrt(D) = 1/32 folded in), split hi/lo
#pragma unroll
    for (int i=0;i<8;i++){
        int id = tid + i*128;
        int r = id>>4, c = (id&15)<<2;
        float4 v4 = *(const float4*)&Qb[(size_t)r*Dc + c];
        float q[4] = {v4.x, v4.y, v4.z, v4.w};
        float hh[4], ll[4];
#pragma unroll
        for (int t=0;t<4;t++){
            float s = q[t]*0.03125f;
            hh[t] = wmma::__float_to_tf32(s);
            ll[t] = s - hh[t];
        }
        *(float4*)&Qh[r*72+c] = make_float4(hh[0],hh[1],hh[2],hh[3]);
        *(float4*)&Ql[r*72+c] = make_float4(ll[0],ll[1],ll[2],ll[3]);
    }
    const int rr = w*16 + (lane>>1);   // S row owned by this lane (2 lanes/row)
    const int hc = (lane&1)*32;        // which half of 64 cols
    float m_run = -1e30f, l_run = 0.0f;

    // ---------------- Pass A: row max & sumexp ----------------
    for (int kt=0; kt<Lc/64; kt++){
#pragma unroll
        for (int i=0;i<8;i++){
            int id = tid + i*128;
            int r = id>>4, c = (id&15)<<2;
            float4 v4 = *(const float4*)&Kb[(size_t)(kt*64+r)*Dc + c];
            float kx[4] = {v4.x,v4.y,v4.z,v4.w};
            float hh[4], ll[4];
#pragma unroll
            for (int t=0;t<4;t++){ hh[t]=wmma::__float_to_tf32(kx[t]); ll[t]=kx[t]-hh[t]; }
            *(float4*)&Kh[r*72+c] = make_float4(hh[0],hh[1],hh[2],hh[3]);
            *(float4*)&Kl[r*72+c] = make_float4(ll[0],ll[1],ll[2],ll[3]);
        }
        __syncthreads();
        qk_tile(Qh, Ql, Kh, Kl, Ss, w);
        __syncwarp();
        float tmax = -1e30f;
#pragma unroll
        for (int jj=0;jj<32;jj++) tmax = fmaxf(tmax, Ss[rr*72+hc+jj]);
        tmax = fmaxf(tmax, __shfl_xor_sync(0xffffffffu, tmax, 1));
        float newm = fmaxf(m_run, tmax);
        float sum = 0.0f;
#pragma unroll
        for (int jj=0;jj<32;jj++) sum += __expf(Ss[rr*72+hc+jj] - newm);
        sum += __shfl_xor_sync(0xffffffffu, sum, 1);
        l_run = l_run * __expf(m_run - newm) + sum;
        m_run = newm;
        __syncthreads();
    }
    float inv_l = 1.0f / l_run;

    // ---------------- Pass B: P = exp(S-m)/l, O += P@V ----------------
    wmma::fragment<wmma::accumulator,16,16,8,float> ofr[4];
#pragma unroll
    for (int n=0;n<4;n++) wmma::fill_fragment(ofr[n], 0.0f);

    for (int kt=0; kt<Lc/64; kt++){
#pragma unroll
        for (int i=0;i<8;i++){
            int id = tid + i*128;
            int r = id>>4, c = (id&15)<<2;
            float4 v4 = *(const float4*)&Kb[(size_t)(kt*64+r)*Dc + c];
            float kx[4] = {v4.x,v4.y,v4.z,v4.w};
            float hh[4], ll[4];
#pragma unroll
            for (int t=0;t<4;t++){ hh[t]=wmma::__float_to_tf32(kx[t]); ll[t]=kx[t]-hh[t]; }
            *(float4*)&Kh[r*72+c] = make_float4(hh[0],hh[1],hh[2],hh[3]);
            *(float4*)&Kl[r*72+c] = make_float4(ll[0],ll[1],ll[2],ll[3]);
            *(float4*)&Vs[r*72+c] = *(const float4*)&Vb[(size_t)(kt*64+r)*Dc + c];
        }
        __syncthreads();
        qk_tile(Qh, Ql, Kh, Kl, Ss, w);
        __syncwarp();
#pragma unroll
        for (int jj=0;jj<32;jj++){
            int idx = rr*72+hc+jj;
            Ss[idx] = __expf(Ss[idx] - m_run) * inv_l;
        }
        __syncwarp();
#pragma unroll
        for (int kk=0;kk<8;kk++){
            wmma::fragment<wmma::matrix_a,16,16,8,wmma::precision::tf32,wmma::row_major> pa;
            wmma::load_matrix_sync(pa, &Ss[(w*16)*72 + kk*8], 72);
#pragma unroll
            for (int t=0;t<pa.num_elements;t++) pa.x[t]=wmma::__float_to_tf32(pa.x[t]);
#pragma unroll
            for (int n=0;n<4;n++){
                wmma::fragment<wmma::matrix_b,16,16,8,wmma::precision::tf32,wmma::row_major> vb;
                wmma::load_matrix_sync(vb, &Vs[(kk*8)*72 + n*16], 72);
#pragma unroll
                for (int t=0;t<vb.num_elements;t++) vb.x[t]=wmma::__float_to_tf32(vb.x[t]);
                wmma::mma_sync(ofr[n], pa, vb, ofr[n]);
            }
        }
        __syncthreads();
    }
#pragma unroll
    for (int n=0;n<4;n++)
        wmma::store_matrix_sync(&O[((size_t)b*Lc + qt*64 + w*16)*Dc + h*64 + n*16],
                                ofr[n], Dc, wmma::mem_row_major);
}

// ---------------------------------------------------------------------------
__global__ __launch_bounds__(256) void bias_add_kernel(
    float* __restrict__ out, const float* __restrict__ bias)
{
    int i = blockIdx.x*256 + threadIdx.x;      // i < NR*Dc/4
    float4 v = ((float4*)out)[i];
    int c = (i<<2) & (Dc-1);
    v.x += bias[c]; v.y += bias[c+1]; v.z += bias[c+2]; v.w += bias[c+3];
    ((float4*)out)[i] = v;
}

// ---------------------------------------------------------------------------
extern "C" void kernel_launch(void* const* d_in, const int* in_sizes, int n_in,
                              void* d_out, int out_size)
{
    const float* x  = (const float*)d_in[0];
    const float* Wq = (const float*)d_in[1];
    const float* bq = (const float*)d_in[2];
    const float* Wk = (const float*)d_in[3];
    const float* bk = (const float*)d_in[4];
    const float* Wv = (const float*)d_in[5];
    const float* bv = (const float*)d_in[6];
    const float* Wo = (const float*)d_in[7];
    const float* bo = (const float*)d_in[8];
    float* out = (float*)d_out;

    float *Qp, *Kp, *Vp, *Tp;
    cudaGetSymbolAddress((void**)&Qp, g_Q);
    cudaGetSymbolAddress((void**)&Kp, g_K);
    cudaGetSymbolAddress((void**)&Vp, g_V);
    cudaGetSymbolAddress((void**)&Tp, g_T);

    dim3 ggrid(Dc/128, NR/128);   // (8, 32)

    // Projections. Reference swaps: K <- x@Wv^T + bv, V <- x@Wk^T + bk.
    gemm_abt<true ><<<ggrid, 256>>>(x, Wq, Qp, Dc, Dc, Dc, Dc);
    gemm_abt<true ><<<ggrid, 256>>>(x, Wv, Kp, Dc, Dc, Dc, Dc);
    gemm_abt<false><<<ggrid, 256>>>(x, Wk, Vp, Dc, Dc, Dc, Dc);

    // bias + xPos rotation (Q uses bq, K uses bv, V uses bk)
    rope_bias_kernel<<<(NR*512)/256, 256>>>(Qp, Kp, Vp, bq, bv, bk);

    // Flash attention
    cudaFuncSetAttribute(flash_kernel,
        cudaFuncAttributeMaxDynamicSharedMemorySize, 6*TSZ*(int)sizeof(float));
    flash_kernel<<<dim3(Lc/64, Bc*Hc), 128, 6*TSZ*(int)sizeof(float)>>>(Qp, Kp, Vp, Tp);

    // Output projection + bias
    gemm_abt<false><<<ggrid, 256>>>(Tp, Wo, out, Dc, Dc, Dc, Dc);
    bias_add_kernel<<<(NR*Dc/4)/256, 256>>>(out, bo);
}

// round 6
// speedup vs baseline: 1.8441x; 1.8441x over previous
#include <cuda_runtime.h>
#include <cuda_bf16.h>
#include <mma.h>
#include <math.h>
#include <stdint.h>

using namespace nvcuda;

#define Bc 2
#define Lc 2048
#define Dc 1024
#define NR (Bc*Lc)

__device__ float g_Q[NR*Dc];
__device__ float g_K[NR*Dc];
__device__ float g_V[NR*Dc];
__device__ float g_T[NR*Dc];

// ---------------------------------------------------------------------------
// bf16 hi/lo split helpers
// ---------------------------------------------------------------------------
__device__ __forceinline__ uint32_t pack2(float a, float b, uint32_t& lo){
    __nv_bfloat16 ha = __float2bfloat16(a), hb = __float2bfloat16(b);
    __nv_bfloat16 la = __float2bfloat16(a - __bfloat162float(ha));
    __nv_bfloat16 lb = __float2bfloat16(b - __bfloat162float(hb));
    lo = (uint32_t)__bfloat16_as_ushort(la) | ((uint32_t)__bfloat16_as_ushort(lb)<<16);
    return (uint32_t)__bfloat16_as_ushort(ha) | ((uint32_t)__bfloat16_as_ushort(hb)<<16);
}
__device__ __forceinline__ void store_split4(void* ph, void* pl, float4 v){
    uint2 H, L;
    H.x = pack2(v.x, v.y, L.x);
    H.y = pack2(v.z, v.w, L.y);
    *(uint2*)ph = H;
    *(uint2*)pl = L;
}

typedef wmma::fragment<wmma::matrix_a,16,16,16,__nv_bfloat16,wmma::row_major> AFrag;
typedef wmma::fragment<wmma::matrix_b,16,16,16,__nv_bfloat16,wmma::col_major> BFragC;
typedef wmma::fragment<wmma::matrix_b,16,16,16,__nv_bfloat16,wmma::row_major> BFragR;
typedef wmma::fragment<wmma::accumulator,16,16,16,float> CFrag;

// ---------------------------------------------------------------------------
// GEMM: C[4096,1024] = A[4096,1024] @ W[1024,1024]^T
// bf16 hi/lo 3-mma split, m16n16k16 wmma. CTA tile 128x128, K-chunk 32,
// register-prefetch double buffering. 8 warps (4x2), warp tile 32x64.
// ---------------------------------------------------------------------------
#define GS 40                       // smem row stride (bf16 elems), 80B rows
#define GMAT (128*GS)               // elems per matrix slice
#define G_SMEM (2*4*GMAT*2)         // 81920 bytes

__global__ __launch_bounds__(256) void gemm_bf16(
    const float* __restrict__ A, const float* __restrict__ W,
    float* __restrict__ C)
{
    extern __shared__ __nv_bfloat16 sm[];
    const int tid = threadIdx.x;
    const int wid = tid>>5;
    const int wm = wid>>1, wn = wid&1;
    const int m0 = blockIdx.y*128, n0 = blockIdx.x*128;

    CFrag acc[2][4];
#pragma unroll
    for (int i=0;i<2;i++)
#pragma unroll
      for (int j=0;j<4;j++) wmma::fill_fragment(acc[i][j], 0.0f);

    const int lr = tid>>3;              // 0..31 ... wait: need 0..127
    // each thread handles 4 float4-groups over a 128x32 tile:
    // id = tid + i*256, r = id>>3 (0..127), c = (id&7)*4 (0..28)
    float4 ra[4], rb[4];

#define LOAD_TILE(k0) do { \
    _Pragma("unroll") \
    for (int i=0;i<4;i++){ \
        int id = tid + i*256; \
        int r = id>>3, c = (id&7)<<2; \
        ra[i] = *(const float4*)&A[(size_t)(m0+r)*Dc + (k0) + c]; \
        rb[i] = *(const float4*)&W[(size_t)(n0+r)*Dc + (k0) + c]; \
    } } while(0)

#define STORE_TILE(buf) do { \
    __nv_bfloat16* Ah = sm + (buf)*4*GMAT; \
    __nv_bfloat16* Al = Ah + GMAT; \
    __nv_bfloat16* Bh = Ah + 2*GMAT; \
    __nv_bfloat16* Bl = Ah + 3*GMAT; \
    _Pragma("unroll") \
    for (int i=0;i<4;i++){ \
        int id = tid + i*256; \
        int r = id>>3, c = (id&7)<<2; \
        size_t boff = 2u*(unsigned)(r*GS + c); \
        store_split4((char*)Ah + boff, (char*)Al + boff, ra[i]); \
        store_split4((char*)Bh + boff, (char*)Bl + boff, rb[i]); \
    } } while(0)

    LOAD_TILE(0);
    STORE_TILE(0);
    __syncthreads();

    for (int ch=0; ch<32; ch++){
        if (ch < 31) LOAD_TILE((ch+1)*32);

        const __nv_bfloat16* Ah = sm + (ch&1)*4*GMAT;
        const __nv_bfloat16* Al = Ah + GMAT;
        const __nv_bfloat16* Bh = Ah + 2*GMAT;
        const __nv_bfloat16* Bl = Ah + 3*GMAT;
#pragma unroll
        for (int st=0; st<2; st++){
            AFrag ah[2], al[2];
#pragma unroll
            for (int im=0;im<2;im++){
                wmma::load_matrix_sync(ah[im], Ah + (wm*32+im*16)*GS + st*16, GS);
                wmma::load_matrix_sync(al[im], Al + (wm*32+im*16)*GS + st*16, GS);
            }
#pragma unroll
            for (int in=0;in<4;in++){
                BFragC bh_, bl_;
                wmma::load_matrix_sync(bh_, Bh + (wn*64+in*16)*GS + st*16, GS);
                wmma::load_matrix_sync(bl_, Bl + (wn*64+in*16)*GS + st*16, GS);
#pragma unroll
                for (int im=0;im<2;im++){
                    wmma::mma_sync(acc[im][in], ah[im], bh_, acc[im][in]);
                    wmma::mma_sync(acc[im][in], ah[im], bl_, acc[im][in]);
                    wmma::mma_sync(acc[im][in], al[im], bh_, acc[im][in]);
                }
            }
        }
        if (ch < 31) STORE_TILE((ch+1)&1);
        __syncthreads();
    }
#pragma unroll
    for (int im=0;im<2;im++)
#pragma unroll
      for (int in=0;in<4;in++)
        wmma::store_matrix_sync(&C[(size_t)(m0+wm*32+im*16)*Dc + n0+wn*64+in*16],
                                acc[im][in], Dc, wmma::mem_row_major);
}

// ---------------------------------------------------------------------------
// xPos rotary + biases (Q uses bq, K uses bv, V uses bk — reference swap).
// ---------------------------------------------------------------------------
__global__ __launch_bounds__(256) void rope_bias_kernel(
    float* __restrict__ Q, float* __restrict__ K, float* __restrict__ V,
    const float* __restrict__ biasQ, const float* __restrict__ biasK,
    const float* __restrict__ biasV)
{
    int p = blockIdx.x*256 + threadIdx.x;     // p < NR*512
    int row = p >> 9;
    int col = (p & 511) << 1;                 // even column in [0,1024)
    int l = row & (Lc-1);
    int j = col & 63;                         // even dim within head
    float jf = (float)j;
    float inv_freq = powf(10000.0f, -jf * (1.0f/64.0f));
    float fr = (float)l * inv_freq;
    float sn, cs; sincosf(fr, &sn, &cs);
    float sv = (jf + 25.6f) * (1.0f/89.6f);
    float pw = ((float)l - 1024.0f) * (1.0f/512.0f);
    float sc = powf(sv, pw);
    float isc = 1.0f/sc;
    size_t base = (size_t)row*Dc + col;

    float q0 = Q[base] + biasQ[col], q1 = Q[base+1] + biasQ[col+1];
    Q[base]   = q0*cs*sc - q1*sn*sc;
    Q[base+1] = q1*cs*sc + q0*sn*sc;

    float k0 = K[base] + biasK[col], k1 = K[base+1] + biasK[col+1];
    K[base]   = k0*cs*isc - k1*sn*isc;
    K[base+1] = k1*cs*isc + k0*sn*isc;

    V[base]   += biasV[col];
    V[base+1] += biasV[col+1];
}

// ---------------------------------------------------------------------------
// Two-pass flash attention, bf16-split wmma (m16n16k16, 3-mma).
// CTA: 128 q-rows x one (b,h); 8 warps, each owns 16 rows. K/V tiles of 64.
// ---------------------------------------------------------------------------
#define SD 88                  // smem stride (elements)
#define OFF_QH 0
#define OFF_QL 22528
#define OFF_KH 45056
#define OFF_KL 56320
#define OFF_VH 67584
#define OFF_VL 78848
#define OFF_SS 90112
#define OFF_PH 135168
#define OFF_PL 157696
#define FL_SMEM 180224

__global__ __launch_bounds__(256) void flash_kernel(
    const float* __restrict__ Q, const float* __restrict__ K,
    const float* __restrict__ V, float* __restrict__ O)
{
    extern __shared__ char smc[];
    __nv_bfloat16* Qh = (__nv_bfloat16*)(smc + OFF_QH);
    __nv_bfloat16* Ql = (__nv_bfloat16*)(smc + OFF_QL);
    __nv_bfloat16* Kh = (__nv_bfloat16*)(smc + OFF_KH);
    __nv_bfloat16* Kl = (__nv_bfloat16*)(smc + OFF_KL);
    __nv_bfloat16* Vh = (__nv_bfloat16*)(smc + OFF_VH);
    __nv_bfloat16* Vl = (__nv_bfloat16*)(smc + OFF_VL);
    float*         Ss = (float*)        (smc + OFF_SS);
    __nv_bfloat16* Ph = (__nv_bfloat16*)(smc + OFF_PH);
    __nv_bfloat16* Pl = (__nv_bfloat16*)(smc + OFF_PL);

    const int tid = threadIdx.x;
    const int w = tid>>5, lane = tid&31;
    const int qt = blockIdx.x, bh = blockIdx.y;
    const int b = bh>>4, h = bh&15;
    const float* Qb = Q + ((size_t)b*Lc + qt*128)*Dc + h*64;
    const float* Kb = K + (size_t)b*Lc*Dc + h*64;
    const float* Vb = V + (size_t)b*Lc*Dc + h*64;

    // Q tile: pre-scale by 1/sqrt(1024)=1/32, split hi/lo bf16
#pragma unroll
    for (int i=0;i<8;i++){
        int idx = tid + i*256;             // 0..2047 groups over 128x64
        int r = idx>>4, c = (idx&15)<<2;
        float4 v4 = *(const float4*)&Qb[(size_t)r*Dc + c];
        v4.x *= 0.03125f; v4.y *= 0.03125f; v4.z *= 0.03125f; v4.w *= 0.03125f;
        size_t boff = 2u*(unsigned)(r*SD + c);
        store_split4((char*)Qh + boff, (char*)Ql + boff, v4);
    }
    __syncthreads();

    // cache Q fragments (fixed for whole CTA lifetime)
    AFrag qfh[4], qfl[4];
#pragma unroll
    for (int kk=0;kk<4;kk++){
        wmma::load_matrix_sync(qfh[kk], Qh + (w*16)*SD + kk*16, SD);
        wmma::load_matrix_sync(qfl[kk], Ql + (w*16)*SD + kk*16, SD);
    }

    const int rr = w*16 + (lane>>1);
    const int hc = (lane&1)*32;
    float m_run = -1e30f, l_run = 0.0f;

    // ---------------- Pass A: row max & sumexp ----------------
    for (int kt=0; kt<Lc/64; kt++){
#pragma unroll
        for (int i=0;i<4;i++){
            int idx = tid + i*256;         // 0..1023 groups over 64x64
            int r = idx>>4, c = (idx&15)<<2;
            float4 v4 = *(const float4*)&Kb[(size_t)(kt*64+r)*Dc + c];
            size_t boff = 2u*(unsigned)(r*SD + c);
            store_split4((char*)Kh + boff, (char*)Kl + boff, v4);
        }
        __syncthreads();

        CFrag sfr[4];
#pragma unroll
        for (int n=0;n<4;n++) wmma::fill_fragment(sfr[n], 0.0f);
#pragma unroll
        for (int kk=0;kk<4;kk++){
#pragma unroll
            for (int n=0;n<4;n++){
                BFragC bhf, blf;
                wmma::load_matrix_sync(bhf, Kh + (n*16)*SD + kk*16, SD);
                wmma::load_matrix_sync(blf, Kl + (n*16)*SD + kk*16, SD);
                wmma::mma_sync(sfr[n], qfh[kk], bhf, sfr[n]);
                wmma::mma_sync(sfr[n], qfh[kk], blf, sfr[n]);
                wmma::mma_sync(sfr[n], qfl[kk], bhf, sfr[n]);
            }
        }
#pragma unroll
        for (int n=0;n<4;n++)
            wmma::store_matrix_sync(&Ss[(w*16)*SD + n*16], sfr[n], SD, wmma::mem_row_major);
        __syncwarp();

        float tmax = -1e30f;
#pragma unroll
        for (int jj=0;jj<32;jj++) tmax = fmaxf(tmax, Ss[rr*SD+hc+jj]);
        tmax = fmaxf(tmax, __shfl_xor_sync(0xffffffffu, tmax, 1));
        float newm = fmaxf(m_run, tmax);
        float sum = 0.0f;
#pragma unroll
        for (int jj=0;jj<32;jj++) sum += __expf(Ss[rr*SD+hc+jj] - newm);
        sum += __shfl_xor_sync(0xffffffffu, sum, 1);
        l_run = l_run * __expf(m_run - newm) + sum;
        m_run = newm;
        __syncthreads();
    }
    const float inv_l = 1.0f / l_run;

    // ---------------- Pass B: P = exp(S-m)/l, O += P@V ----------------
    CFrag ofr[4];
#pragma unroll
    for (int n=0;n<4;n++) wmma::fill_fragment(ofr[n], 0.0f);

    for (int kt=0; kt<Lc/64; kt++){
#pragma unroll
        for (int i=0;i<4;i++){
            int idx = tid + i*256;
            int r = idx>>4, c = (idx&15)<<2;
            float4 k4 = *(const float4*)&Kb[(size_t)(kt*64+r)*Dc + c];
            float4 v4 = *(const float4*)&Vb[(size_t)(kt*64+r)*Dc + c];
            size_t boff = 2u*(unsigned)(r*SD + c);
            store_split4((char*)Kh + boff, (char*)Kl + boff, k4);
            store_split4((char*)Vh + boff, (char*)Vl + boff, v4);
        }
        __syncthreads();

        CFrag sfr[4];
#pragma unroll
        for (int n=0;n<4;n++) wmma::fill_fragment(sfr[n], 0.0f);
#pragma unroll
        for (int kk=0;kk<4;kk++){
#pragma unroll
            for (int n=0;n<4;n++){
                BFragC bhf, blf;
                wmma::load_matrix_sync(bhf, Kh + (n*16)*SD + kk*16, SD);
                wmma::load_matrix_sync(blf, Kl + (n*16)*SD + kk*16, SD);
                wmma::mma_sync(sfr[n], qfh[kk], bhf, sfr[n]);
                wmma::mma_sync(sfr[n], qfh[kk], blf, sfr[n]);
                wmma::mma_sync(sfr[n], qfl[kk], bhf, sfr[n]);
            }
        }
#pragma unroll
        for (int n=0;n<4;n++)
            wmma::store_matrix_sync(&Ss[(w*16)*SD + n*16], sfr[n], SD, wmma::mem_row_major);
        __syncwarp();

        // exp + normalize, split into bf16 hi/lo (warp-local rows only)
#pragma unroll
        for (int jj=0;jj<32;jj++){
            int idx = rr*SD + hc + jj;
            float pv = __expf(Ss[idx] - m_run) * inv_l;
            __nv_bfloat16 hi = __float2bfloat16(pv);
            Ph[idx] = hi;
            Pl[idx] = __float2bfloat16(pv - __bfloat162float(hi));
        }
        __syncwarp();

        // O += P @ V   (split P, split V, 3-mma)
#pragma unroll
        for (int kk=0;kk<4;kk++){
            AFrag pah, pal;
            wmma::load_matrix_sync(pah, Ph + (w*16)*SD + kk*16, SD);
            wmma::load_matrix_sync(pal, Pl + (w*16)*SD + kk*16, SD);
#pragma unroll
            for (int n=0;n<4;n++){
                BFragR vbh, vbl;
                wmma::load_matrix_sync(vbh, Vh + (kk*16)*SD + n*16, SD);
                wmma::load_matrix_sync(vbl, Vl + (kk*16)*SD + n*16, SD);
                wmma::mma_sync(ofr[n], pah, vbh, ofr[n]);
                wmma::mma_sync(ofr[n], pah, vbl, ofr[n]);
                wmma::mma_sync(ofr[n], pal, vbh, ofr[n]);
            }
        }
        __syncthreads();
    }
#pragma unroll
    for (int n=0;n<4;n++)
        wmma::store_matrix_sync(&O[((size_t)b*Lc + qt*128 + w*16)*Dc + h*64 + n*16],
                                ofr[n], Dc, wmma::mem_row_major);
}

// ---------------------------------------------------------------------------
__global__ __launch_bounds__(256) void bias_add_kernel(
    float* __restrict__ out, const float* __restrict__ bias)
{
    int i = blockIdx.x*256 + threadIdx.x;      // i < NR*Dc/4
    float4 v = ((float4*)out)[i];
    int c = (i<<2) & (Dc-1);
    v.x += bias[c]; v.y += bias[c+1]; v.z += bias[c+2]; v.w += bias[c+3];
    ((float4*)out)[i] = v;
}

// ---------------------------------------------------------------------------
extern "C" void kernel_launch(void* const* d_in, const int* in_sizes, int n_in,
                              void* d_out, int out_size)
{
    const float* x  = (const float*)d_in[0];
    const float* Wq = (const float*)d_in[1];
    const float* bq = (const float*)d_in[2];
    const float* Wk = (const float*)d_in[3];
    const float* bk = (const float*)d_in[4];
    const float* Wv = (const float*)d_in[5];
    const float* bv = (const float*)d_in[6];
    const float* Wo = (const float*)d_in[7];
    const float* bo = (const float*)d_in[8];
    float* out = (float*)d_out;

    float *Qp, *Kp, *Vp, *Tp;
    cudaGetSymbolAddress((void**)&Qp, g_Q);
    cudaGetSymbolAddress((void**)&Kp, g_K);
    cudaGetSymbolAddress((void**)&Vp, g_V);
    cudaGetSymbolAddress((void**)&Tp, g_T);

    cudaFuncSetAttribute(gemm_bf16, cudaFuncAttributeMaxDynamicSharedMemorySize, G_SMEM);
    cudaFuncSetAttribute(flash_kernel, cudaFuncAttributeMaxDynamicSharedMemorySize, FL_SMEM);

    dim3 ggrid(Dc/128, NR/128);   // (8, 32)

    // Projections. Reference swaps: K <- x@Wv^T (+bv), V <- x@Wk^T (+bk).
    gemm_bf16<<<ggrid, 256, G_SMEM>>>(x, Wq, Qp);
    gemm_bf16<<<ggrid, 256, G_SMEM>>>(x, Wv, Kp);
    gemm_bf16<<<ggrid, 256, G_SMEM>>>(x, Wk, Vp);

    // biases + xPos rotation (Q uses bq, K uses bv, V uses bk)
    rope_bias_kernel<<<(NR*512)/256, 256>>>(Qp, Kp, Vp, bq, bv, bk);

    // Flash attention
    flash_kernel<<<dim3(Lc/128, Bc*16), 256, FL_SMEM>>>(Qp, Kp, Vp, Tp);

    // Output projection + bias
    gemm_bf16<<<ggrid, 256, G_SMEM>>>(Tp, Wo, out);
    bias_add_kernel<<<(NR*Dc/4)/256, 256>>>(out, bo);
}

// round 8
// speedup vs baseline: 2.9300x; 1.5888x over previous
#include <cuda_runtime.h>
#include <cuda_bf16.h>
#include <mma.h>
#include <math.h>
#include <stdint.h>

using namespace nvcuda;

#define Bc 2
#define Lc 2048
#define Dc 1024
#define NR (Bc*Lc)

__device__ float g_Q[NR*Dc];
__device__ float g_K[NR*Dc];
__device__ float g_V[NR*Dc];
__device__ float g_T[NR*Dc];

// ---------------------------------------------------------------------------
// bf16 hi/lo split helpers
// ---------------------------------------------------------------------------
__device__ __forceinline__ uint32_t pack2(float a, float b, uint32_t& lo){
    __nv_bfloat16 ha = __float2bfloat16(a), hb = __float2bfloat16(b);
    __nv_bfloat16 la = __float2bfloat16(a - __bfloat162float(ha));
    __nv_bfloat16 lb = __float2bfloat16(b - __bfloat162float(hb));
    lo = (uint32_t)__bfloat16_as_ushort(la) | ((uint32_t)__bfloat16_as_ushort(lb)<<16);
    return (uint32_t)__bfloat16_as_ushort(ha) | ((uint32_t)__bfloat16_as_ushort(hb)<<16);
}
__device__ __forceinline__ void store_split4(void* ph, void* pl, float4 v){
    uint2 H, L;
    H.x = pack2(v.x, v.y, L.x);
    H.y = pack2(v.z, v.w, L.y);
    *(uint2*)ph = H;
    *(uint2*)pl = L;
}

typedef wmma::fragment<wmma::matrix_a,16,16,16,__nv_bfloat16,wmma::row_major> AFrag;
typedef wmma::fragment<wmma::matrix_b,16,16,16,__nv_bfloat16,wmma::col_major> BFragC;
typedef wmma::fragment<wmma::accumulator,16,16,16,float> CFrag;

// ---------------------------------------------------------------------------
// raw mma/ldmatrix primitives (baseline sm_80+ features, OK for compute_103)
// ---------------------------------------------------------------------------
__device__ __forceinline__ uint32_t smem_u32(const void* p){
    uint32_t a;
    asm("{ .reg .u64 t; cvta.to.shared.u64 t, %1; cvt.u32.u64 %0, t; }"
        : "=r"(a) : "l"(p));
    return a;
}
__device__ __forceinline__ void mma16816(float* d, const uint32_t* a, const uint32_t* b){
    asm volatile(
        "mma.sync.aligned.m16n8k16.row.col.f32.bf16.bf16.f32 "
        "{%0,%1,%2,%3}, {%4,%5,%6,%7}, {%8,%9}, {%0,%1,%2,%3};"
        : "+f"(d[0]), "+f"(d[1]), "+f"(d[2]), "+f"(d[3])
        : "r"(a[0]), "r"(a[1]), "r"(a[2]), "r"(a[3]), "r"(b[0]), "r"(b[1]));
}
__device__ __forceinline__ void ldsm4(uint32_t* r, uint32_t addr){
    asm volatile("ldmatrix.sync.aligned.m8n8.x4.shared.b16 {%0,%1,%2,%3}, [%4];"
        : "=r"(r[0]), "=r"(r[1]), "=r"(r[2]), "=r"(r[3]) : "r"(addr));
}
__device__ __forceinline__ void ldsm2(uint32_t* r, uint32_t addr){
    asm volatile("ldmatrix.sync.aligned.m8n8.x2.shared.b16 {%0,%1}, [%2];"
        : "=r"(r[0]), "=r"(r[1]) : "r"(addr));
}
__device__ __forceinline__ void ldsm2t(uint32_t* r, uint32_t addr){
    asm volatile("ldmatrix.sync.aligned.m8n8.x2.trans.shared.b16 {%0,%1}, [%2];"
        : "=r"(r[0]), "=r"(r[1]) : "r"(addr));
}

// ---------------------------------------------------------------------------
// GEMM: C[4096,1024] = A[4096,1024] @ W[1024,1024]^T  (unchanged from R6)
// ---------------------------------------------------------------------------
#define GS 40
#define GMAT (128*GS)
#define G_SMEM (2*4*GMAT*2)

__global__ __launch_bounds__(256) void gemm_bf16(
    const float* __restrict__ A, const float* __restrict__ W,
    float* __restrict__ C)
{
    extern __shared__ __nv_bfloat16 sm[];
    const int tid = threadIdx.x;
    const int wid = tid>>5;
    const int wm = wid>>1, wn = wid&1;
    const int m0 = blockIdx.y*128, n0 = blockIdx.x*128;

    CFrag acc[2][4];
#pragma unroll
    for (int i=0;i<2;i++)
#pragma unroll
      for (int j=0;j<4;j++) wmma::fill_fragment(acc[i][j], 0.0f);

    float4 ra[4], rb[4];

#define LOAD_TILE(k0) do { \
    _Pragma("unroll") \
    for (int i=0;i<4;i++){ \
        int id = tid + i*256; \
        int r = id>>3, c = (id&7)<<2; \
        ra[i] = *(const float4*)&A[(size_t)(m0+r)*Dc + (k0) + c]; \
        rb[i] = *(const float4*)&W[(size_t)(n0+r)*Dc + (k0) + c]; \
    } } while(0)

#define STORE_TILE(buf) do { \
    __nv_bfloat16* Ah = sm + (buf)*4*GMAT; \
    __nv_bfloat16* Al = Ah + GMAT; \
    __nv_bfloat16* Bh = Ah + 2*GMAT; \
    __nv_bfloat16* Bl = Ah + 3*GMAT; \
    _Pragma("unroll") \
    for (int i=0;i<4;i++){ \
        int id = tid + i*256; \
        int r = id>>3, c = (id&7)<<2; \
        size_t boff = 2u*(unsigned)(r*GS + c); \
        store_split4((char*)Ah + boff, (char*)Al + boff, ra[i]); \
        store_split4((char*)Bh + boff, (char*)Bl + boff, rb[i]); \
    } } while(0)

    LOAD_TILE(0);
    STORE_TILE(0);
    __syncthreads();

    for (int ch=0; ch<32; ch++){
        if (ch < 31) LOAD_TILE((ch+1)*32);

        const __nv_bfloat16* Ah = sm + (ch&1)*4*GMAT;
        const __nv_bfloat16* Al = Ah + GMAT;
        const __nv_bfloat16* Bh = Ah + 2*GMAT;
        const __nv_bfloat16* Bl = Ah + 3*GMAT;
#pragma unroll
        for (int st=0; st<2; st++){
            AFrag ah[2], al[2];
#pragma unroll
            for (int im=0;im<2;im++){
                wmma::load_matrix_sync(ah[im], Ah + (wm*32+im*16)*GS + st*16, GS);
                wmma::load_matrix_sync(al[im], Al + (wm*32+im*16)*GS + st*16, GS);
            }
#pragma unroll
            for (int in=0;in<4;in++){
                BFragC bh_, bl_;
                wmma::load_matrix_sync(bh_, Bh + (wn*64+in*16)*GS + st*16, GS);
                wmma::load_matrix_sync(bl_, Bl + (wn*64+in*16)*GS + st*16, GS);
#pragma unroll
                for (int im=0;im<2;im++){
                    wmma::mma_sync(acc[im][in], ah[im], bh_, acc[im][in]);
                    wmma::mma_sync(acc[im][in], ah[im], bl_, acc[im][in]);
                    wmma::mma_sync(acc[im][in], al[im], bh_, acc[im][in]);
                }
            }
        }
        if (ch < 31) STORE_TILE((ch+1)&1);
        __syncthreads();
    }
#pragma unroll
    for (int im=0;im<2;im++)
#pragma unroll
      for (int in=0;in<4;in++)
        wmma::store_matrix_sync(&C[(size_t)(m0+wm*32+im*16)*Dc + n0+wn*64+in*16],
                                acc[im][in], Dc, wmma::mem_row_major);
}

// ---------------------------------------------------------------------------
// xPos rotary + biases (Q uses bq, K uses bv, V uses bk — reference swap).
// ---------------------------------------------------------------------------
__global__ __launch_bounds__(256) void rope_bias_kernel(
    float* __restrict__ Q, float* __restrict__ K, float* __restrict__ V,
    const float* __restrict__ biasQ, const float* __restrict__ biasK,
    const float* __restrict__ biasV)
{
    int p = blockIdx.x*256 + threadIdx.x;     // p < NR*512
    int row = p >> 9;
    int col = (p & 511) << 1;                 // even column in [0,1024)
    int l = row & (Lc-1);
    int j = col & 63;
    float jf = (float)j;
    float inv_freq = powf(10000.0f, -jf * (1.0f/64.0f));
    float fr = (float)l * inv_freq;
    float sn, cs; sincosf(fr, &sn, &cs);
    float sv = (jf + 25.6f) * (1.0f/89.6f);
    float pw = ((float)l - 1024.0f) * (1.0f/512.0f);
    float sc = powf(sv, pw);
    float isc = 1.0f/sc;
    size_t base = (size_t)row*Dc + col;

    float q0 = Q[base] + biasQ[col], q1 = Q[base+1] + biasQ[col+1];
    Q[base]   = q0*cs*sc - q1*sn*sc;
    Q[base+1] = q1*cs*sc + q0*sn*sc;

    float k0 = K[base] + biasK[col], k1 = K[base+1] + biasK[col+1];
    K[base]   = k0*cs*isc - k1*sn*isc;
    K[base+1] = k1*cs*isc + k0*sn*isc;

    V[base]   += biasV[col];
    V[base+1] += biasV[col+1];
}

// ---------------------------------------------------------------------------
// Single-pass FA2 flash attention, raw mma.m16n8k16, bf16 3-mma split.
// CTA: 128 q-rows x one (b,h); 8 warps x 16 rows. K/V tiles of 64 keys.
// S and P live in registers; online softmax rescale on register O accums.
// ---------------------------------------------------------------------------
#define FSD 72                            // smem row stride (bf16 elems)
#define FTILE (64*FSD*2)                  // 9216 bytes per 64x64 bf16 slice
#define FL_SMEM (4*FTILE)                 // Kh,Kl,Vh,Vl = 36864

__global__ __launch_bounds__(256) void flash_kernel(
    const float* __restrict__ Q, const float* __restrict__ K,
    const float* __restrict__ V, float* __restrict__ O)
{
    extern __shared__ char smc[];
    __nv_bfloat16* Kh = (__nv_bfloat16*)(smc);
    __nv_bfloat16* Kl = (__nv_bfloat16*)(smc + FTILE);
    __nv_bfloat16* Vh = (__nv_bfloat16*)(smc + 2*FTILE);
    __nv_bfloat16* Vl = (__nv_bfloat16*)(smc + 3*FTILE);
    // Q staging aliases the same smem (used before the K/V loop starts)
    __nv_bfloat16* Qh = (__nv_bfloat16*)(smc);
    __nv_bfloat16* Ql = (__nv_bfloat16*)(smc + 2*FTILE);

    const int tid = threadIdx.x;
    const int w = tid>>5, L = tid&31;
    const int lr = L&7, sel = (L>>3)&1;
    const int qt = blockIdx.x, bh = blockIdx.y;
    const int b = bh>>4, h = bh&15;
    const float* Qb = Q + ((size_t)b*Lc + qt*128)*Dc + h*64;
    const float* Kb = K + (size_t)b*Lc*Dc + h*64;
    const float* Vb = V + (size_t)b*Lc*Dc + h*64;

    // ---- stage Q (pre-scaled by 1/sqrt(1024)=1/32), split hi/lo ----
#pragma unroll
    for (int i=0;i<8;i++){
        int idx = tid + i*256;            // 128x64 floats = 2048 float4-groups
        int r = idx>>4, c = (idx&15)<<2;
        float4 v4 = *(const float4*)&Qb[(size_t)r*Dc + c];
        v4.x *= 0.03125f; v4.y *= 0.03125f; v4.z *= 0.03125f; v4.w *= 0.03125f;
        size_t boff = 2u*(unsigned)(r*FSD + c);
        store_split4((char*)Qh + boff, (char*)Ql + boff, v4);
    }
    __syncthreads();

    // ---- Q fragments to registers (A-operand, m16k16 per ktile) ----
    uint32_t qh[4][4], ql[4][4];
    {
        int g = L>>3;
        int qrow = w*16 + (g&1)*8 + lr;
        int qcol = (g>>1)*8;
#pragma unroll
        for (int kk=0;kk<4;kk++){
            ldsm4(qh[kk], smem_u32(Qh + qrow*FSD + kk*16 + qcol));
            ldsm4(ql[kk], smem_u32(Ql + qrow*FSD + kk*16 + qcol));
        }
    }
    __syncthreads();    // Q smem free; K/V may now overwrite

    float Oa[8][4];
#pragma unroll
    for (int n=0;n<8;n++){ Oa[n][0]=0.f; Oa[n][1]=0.f; Oa[n][2]=0.f; Oa[n][3]=0.f; }
    float m0r = -1e30f, m1r = -1e30f, l0r = 0.f, l1r = 0.f;

    float4 pk[4], pv4[4];
#pragma unroll
    for (int i=0;i<4;i++){
        int idx = tid + i*256;            // 64x64 floats = 1024 float4-groups
        int r = idx>>4, c = (idx&15)<<2;
        pk[i]  = *(const float4*)&Kb[(size_t)r*Dc + c];
        pv4[i] = *(const float4*)&Vb[(size_t)r*Dc + c];
    }

    for (int kt=0; kt<Lc/64; kt++){
        if (kt > 0) __syncthreads();      // previous tile fully consumed
#pragma unroll
        for (int i=0;i<4;i++){
            int idx = tid + i*256;
            int r = idx>>4, c = (idx&15)<<2;
            size_t boff = 2u*(unsigned)(r*FSD + c);
            store_split4((char*)Kh + boff, (char*)Kl + boff, pk[i]);
            store_split4((char*)Vh + boff, (char*)Vl + boff, pv4[i]);
        }
        __syncthreads();

        if (kt < Lc/64 - 1){              // prefetch next tile (overlaps mma)
#pragma unroll
            for (int i=0;i<4;i++){
                int idx = tid + i*256;
                int r = idx>>4, c = (idx&15)<<2;
                pk[i]  = *(const float4*)&Kb[(size_t)((kt+1)*64+r)*Dc + c];
                pv4[i] = *(const float4*)&Vb[(size_t)((kt+1)*64+r)*Dc + c];
            }
        }

        // ---- S = Q K^T over this 64-key tile (8 n8 blocks) ----
        float S[8][4];
#pragma unroll
        for (int j=0;j<8;j++){ S[j][0]=0.f; S[j][1]=0.f; S[j][2]=0.f; S[j][3]=0.f; }
#pragma unroll
        for (int kk=0;kk<4;kk++){
#pragma unroll
            for (int j=0;j<8;j++){
                uint32_t kbh[2], kbl[2];
                uint32_t a = (uint32_t)((j*8 + lr)*FSD + kk*16 + sel*8);
                ldsm2(kbh, smem_u32(Kh + a));
                ldsm2(kbl, smem_u32(Kl + a));
                mma16816(S[j], qh[kk], kbh);
                mma16816(S[j], qh[kk], kbl);
                mma16816(S[j], ql[kk], kbh);
            }
        }

        // ---- online softmax (rows: r0 = L/4, r1 = L/4+8) ----
        float lm0 = -1e30f, lm1 = -1e30f;
#pragma unroll
        for (int j=0;j<8;j++){
            lm0 = fmaxf(lm0, fmaxf(S[j][0], S[j][1]));
            lm1 = fmaxf(lm1, fmaxf(S[j][2], S[j][3]));
        }
        lm0 = fmaxf(lm0, __shfl_xor_sync(0xffffffffu, lm0, 1));
        lm0 = fmaxf(lm0, __shfl_xor_sync(0xffffffffu, lm0, 2));
        lm1 = fmaxf(lm1, __shfl_xor_sync(0xffffffffu, lm1, 1));
        lm1 = fmaxf(lm1, __shfl_xor_sync(0xffffffffu, lm1, 2));
        float mn0 = fmaxf(m0r, lm0), mn1 = fmaxf(m1r, lm1);
        float al0 = __expf(m0r - mn0), al1 = __expf(m1r - mn1);
        m0r = mn0; m1r = mn1;
        l0r *= al0; l1r *= al1;
#pragma unroll
        for (int n=0;n<8;n++){
            Oa[n][0] *= al0; Oa[n][1] *= al0;
            Oa[n][2] *= al1; Oa[n][3] *= al1;
        }

        float s0 = 0.f, s1 = 0.f;
#pragma unroll
        for (int j=0;j<8;j++){
            S[j][0] = __expf(S[j][0] - mn0);
            S[j][1] = __expf(S[j][1] - mn0);
            S[j][2] = __expf(S[j][2] - mn1);
            S[j][3] = __expf(S[j][3] - mn1);
            s0 += S[j][0] + S[j][1];
            s1 += S[j][2] + S[j][3];
        }
        s0 += __shfl_xor_sync(0xffffffffu, s0, 1);
        s0 += __shfl_xor_sync(0xffffffffu, s0, 2);
        s1 += __shfl_xor_sync(0xffffffffu, s1, 1);
        s1 += __shfl_xor_sync(0xffffffffu, s1, 2);
        l0r += s0; l1r += s1;

        // ---- P (accumulator layout == A-operand layout), split hi/lo ----
        uint32_t ph[4][4], pl[4][4];
#pragma unroll
        for (int t=0;t<4;t++){
            ph[t][0] = pack2(S[2*t][0],   S[2*t][1],   pl[t][0]);
            ph[t][1] = pack2(S[2*t][2],   S[2*t][3],   pl[t][1]);
            ph[t][2] = pack2(S[2*t+1][0], S[2*t+1][1], pl[t][2]);
            ph[t][3] = pack2(S[2*t+1][2], S[2*t+1][3], pl[t][3]);
        }

        // ---- O += P V ----
#pragma unroll
        for (int t=0;t<4;t++){
#pragma unroll
            for (int n=0;n<8;n++){
                uint32_t vbh[2], vbl[2];
                uint32_t a = (uint32_t)((t*16 + sel*8 + lr)*FSD + n*8);
                ldsm2t(vbh, smem_u32(Vh + a));
                ldsm2t(vbl, smem_u32(Vl + a));
                mma16816(Oa[n], ph[t], vbh);
                mma16816(Oa[n], ph[t], vbl);
                mma16816(Oa[n], pl[t], vbh);
            }
        }
    }

    // ---- normalize + store ----
    float inv0 = 1.0f / l0r, inv1 = 1.0f / l1r;
    size_t row0 = (size_t)b*Lc + qt*128 + w*16 + (L>>2);
    size_t row1 = row0 + 8;
    int colb = h*64 + 2*(L&3);
#pragma unroll
    for (int n=0;n<8;n++){
        float2 o0 = make_float2(Oa[n][0]*inv0, Oa[n][1]*inv0);
        float2 o1 = make_float2(Oa[n][2]*inv1, Oa[n][3]*inv1);
        *(float2*)&O[row0*Dc + colb + n*8] = o0;
        *(float2*)&O[row1*Dc + colb + n*8] = o1;
    }
}

// ---------------------------------------------------------------------------
__global__ __launch_bounds__(256) void bias_add_kernel(
    float* __restrict__ out, const float* __restrict__ bias)
{
    int i = blockIdx.x*256 + threadIdx.x;
    float4 v = ((float4*)out)[i];
    int c = (i<<2) & (Dc-1);
    v.x += bias[c]; v.y += bias[c+1]; v.z += bias[c+2]; v.w += bias[c+3];
    ((float4*)out)[i] = v;
}

// ---------------------------------------------------------------------------
extern "C" void kernel_launch(void* const* d_in, const int* in_sizes, int n_in,
                              void* d_out, int out_size)
{
    const float* x  = (const float*)d_in[0];
    const float* Wq = (const float*)d_in[1];
    const float* bq = (const float*)d_in[2];
    const float* Wk = (const float*)d_in[3];
    const float* bk = (const float*)d_in[4];
    const float* Wv = (const float*)d_in[5];
    const float* bv = (const float*)d_in[6];
    const float* Wo = (const float*)d_in[7];
    const float* bo = (const float*)d_in[8];
    float* out = (float*)d_out;

    float *Qp, *Kp, *Vp, *Tp;
    cudaGetSymbolAddress((void**)&Qp, g_Q);
    cudaGetSymbolAddress((void**)&Kp, g_K);
    cudaGetSymbolAddress((void**)&Vp, g_V);
    cudaGetSymbolAddress((void**)&Tp, g_T);

    cudaFuncSetAttribute(gemm_bf16, cudaFuncAttributeMaxDynamicSharedMemorySize, G_SMEM);
    cudaFuncSetAttribute(flash_kernel, cudaFuncAttributeMaxDynamicSharedMemorySize, FL_SMEM);

    dim3 ggrid(Dc/128, NR/128);   // (8, 32)

    // Projections. Reference swaps: K <- x@Wv^T (+bv), V <- x@Wk^T (+bk).
    gemm_bf16<<<ggrid, 256, G_SMEM>>>(x, Wq, Qp);
    gemm_bf16<<<ggrid, 256, G_SMEM>>>(x, Wv, Kp);
    gemm_bf16<<<ggrid, 256, G_SMEM>>>(x, Wk, Vp);

    // biases + xPos rotation (Q uses bq, K uses bv, V uses bk)
    rope_bias_kernel<<<(NR*512)/256, 256>>>(Qp, Kp, Vp, bq, bv, bk);

    // Single-pass flash attention
    flash_kernel<<<dim3(Lc/128, Bc*16), 256, FL_SMEM>>>(Qp, Kp, Vp, Tp);

    // Output projection + bias
    gemm_bf16<<<ggrid, 256, G_SMEM>>>(Tp, Wo, out);
    bias_add_kernel<<<(NR*Dc/4)/256, 256>>>(out, bo);
}

// round 10
// speedup vs baseline: 3.2272x; 1.1014x over previous
#include <cuda_runtime.h>
#include <cuda_bf16.h>
#include <mma.h>
#include <math.h>
#include <stdint.h>

using namespace nvcuda;

#define Bc 2
#define Lc 2048
#define Dc 1024
#define NR (Bc*Lc)
#define DD (Dc*Dc)

// f32 projection outputs
__device__ float g_Q[NR*Dc];
__device__ float g_K[NR*Dc];
__device__ float g_V[NR*Dc];
// pre-split bf16 operands
__device__ __nv_bfloat16 g_xh[NR*Dc], g_xl[NR*Dc];
__device__ __nv_bfloat16 g_Wh[4*DD],  g_Wl[4*DD];
__device__ __nv_bfloat16 g_Qh[NR*Dc], g_Ql[NR*Dc];
__device__ __nv_bfloat16 g_Kh[NR*Dc], g_Kl[NR*Dc];
__device__ __nv_bfloat16 g_Vh[NR*Dc], g_Vl[NR*Dc];
__device__ __nv_bfloat16 g_Th[NR*Dc], g_Tl[NR*Dc];

// ---------------------------------------------------------------------------
// helpers
// ---------------------------------------------------------------------------
__device__ __forceinline__ uint32_t smem_u32(const void* p){
    uint32_t a;
    asm("{ .reg .u64 t; cvta.to.shared.u64 t, %1; cvt.u32.u64 %0, t; }"
        : "=r"(a) : "l"(p));
    return a;
}
__device__ __forceinline__ uint32_t pack2(float a, float b, uint32_t& lo){
    __nv_bfloat16 ha = __float2bfloat16(a), hb = __float2bfloat16(b);
    __nv_bfloat16 la = __float2bfloat16(a - __bfloat162float(ha));
    __nv_bfloat16 lb = __float2bfloat16(b - __bfloat162float(hb));
    lo = (uint32_t)__bfloat16_as_ushort(la) | ((uint32_t)__bfloat16_as_ushort(lb)<<16);
    return (uint32_t)__bfloat16_as_ushort(ha) | ((uint32_t)__bfloat16_as_ushort(hb)<<16);
}
__device__ __forceinline__ void store_split4(void* ph, void* pl, float4 v){
    uint2 H, L;
    H.x = pack2(v.x, v.y, L.x);
    H.y = pack2(v.z, v.w, L.y);
    *(uint2*)ph = H;
    *(uint2*)pl = L;
}
__device__ __forceinline__ void cpasync16(uint32_t saddr, const void* g){
    asm volatile("cp.async.ca.shared.global [%0], [%1], 16;" :: "r"(saddr), "l"(g));
}
#define CP_COMMIT() asm volatile("cp.async.commit_group;" ::: "memory")
#define CP_WAIT1()  asm volatile("cp.async.wait_group 1;" ::: "memory")
#define CP_WAIT0()  asm volatile("cp.async.wait_group 0;" ::: "memory")

__device__ __forceinline__ void mma16816(float* d, const uint32_t* a, const uint32_t* b){
    asm volatile(
        "mma.sync.aligned.m16n8k16.row.col.f32.bf16.bf16.f32 "
        "{%0,%1,%2,%3}, {%4,%5,%6,%7}, {%8,%9}, {%0,%1,%2,%3};"
        : "+f"(d[0]), "+f"(d[1]), "+f"(d[2]), "+f"(d[3])
        : "r"(a[0]), "r"(a[1]), "r"(a[2]), "r"(a[3]), "r"(b[0]), "r"(b[1]));
}
__device__ __forceinline__ void ldsm4(uint32_t* r, uint32_t addr){
    asm volatile("ldmatrix.sync.aligned.m8n8.x4.shared.b16 {%0,%1,%2,%3}, [%4];"
        : "=r"(r[0]), "=r"(r[1]), "=r"(r[2]), "=r"(r[3]) : "r"(addr));
}
__device__ __forceinline__ void ldsm2(uint32_t* r, uint32_t addr){
    asm volatile("ldmatrix.sync.aligned.m8n8.x2.shared.b16 {%0,%1}, [%2];"
        : "=r"(r[0]), "=r"(r[1]) : "r"(addr));
}
__device__ __forceinline__ void ldsm2t(uint32_t* r, uint32_t addr){
    asm volatile("ldmatrix.sync.aligned.m8n8.x2.trans.shared.b16 {%0,%1}, [%2];"
        : "=r"(r[0]), "=r"(r[1]) : "r"(addr));
}

typedef wmma::fragment<wmma::matrix_a,16,16,16,__nv_bfloat16,wmma::row_major> AFrag;
typedef wmma::fragment<wmma::matrix_b,16,16,16,__nv_bfloat16,wmma::col_major> BFragC;
typedef wmma::fragment<wmma::accumulator,16,16,16,float> CFrag;

// ---------------------------------------------------------------------------
// split f32 -> (hi, lo) bf16
// ---------------------------------------------------------------------------
__global__ __launch_bounds__(256) void split_kernel(
    const float* __restrict__ in, __nv_bfloat16* __restrict__ hi,
    __nv_bfloat16* __restrict__ lo)
{
    int i = blockIdx.x*256 + threadIdx.x;
    float4 v = ((const float4*)in)[i];
    store_split4(hi + 4*(size_t)i, lo + 4*(size_t)i, v);
}

// ---------------------------------------------------------------------------
// GEMM: C[4096,1024] = A @ W^T, operands pre-split bf16, cp.async pipelined.
// CTA tile 128x128, K-chunk 32, 8 warps (4x2), warp tile 32x64, 3-mma split.
// ---------------------------------------------------------------------------
#define GS 40
#define GMAT (128*GS)
#define G_SMEM (2*4*GMAT*2)       // 81920 bytes

__global__ __launch_bounds__(256) void gemm_split(
    const __nv_bfloat16* __restrict__ Agh, const __nv_bfloat16* __restrict__ Agl,
    const __nv_bfloat16* __restrict__ Bgh, const __nv_bfloat16* __restrict__ Bgl,
    float* __restrict__ C)
{
    extern __shared__ __nv_bfloat16 sm[];
    uint32_t sbase = smem_u32(sm);
    const int tid = threadIdx.x, wid = tid>>5;
    const int wm = wid>>1, wn = wid&1;
    const int m0 = blockIdx.y*128, n0 = blockIdx.x*128;

    CFrag acc[2][4];
#pragma unroll
    for (int i=0;i<2;i++)
#pragma unroll
      for (int j=0;j<4;j++) wmma::fill_fragment(acc[i][j], 0.0f);

#define G_LOAD(k0, bsel) do { \
    uint32_t s0 = sbase + (uint32_t)((bsel)*4*GMAT)*2; \
    _Pragma("unroll") \
    for (int i=0;i<2;i++){ \
        int g = tid + i*256; \
        int r = g>>2, c8 = g&3; \
        uint32_t so = s0 + (uint32_t)(r*GS + c8*8)*2; \
        size_t ga = (size_t)(m0+r)*Dc + (k0) + c8*8; \
        size_t gb = (size_t)(n0+r)*Dc + (k0) + c8*8; \
        cpasync16(so,              Agh + ga); \
        cpasync16(so + 2*GMAT,     Agl + ga); \
        cpasync16(so + 4*GMAT,     Bgh + gb); \
        cpasync16(so + 6*GMAT,     Bgl + gb); \
    } } while(0)

    G_LOAD(0, 0);
    CP_COMMIT();

    for (int ch=0; ch<32; ch++){
        if (ch < 31){ G_LOAD((ch+1)*32, (ch+1)&1); CP_COMMIT(); CP_WAIT1(); }
        else CP_WAIT0();
        __syncthreads();

        const __nv_bfloat16* Ah = sm + (ch&1)*4*GMAT;
        const __nv_bfloat16* Al = Ah + GMAT;
        const __nv_bfloat16* Bh = Ah + 2*GMAT;
        const __nv_bfloat16* Bl = Ah + 3*GMAT;
#pragma unroll
        for (int st=0; st<2; st++){
            AFrag ah[2], al[2];
#pragma unroll
            for (int im=0;im<2;im++){
                wmma::load_matrix_sync(ah[im], Ah + (wm*32+im*16)*GS + st*16, GS);
                wmma::load_matrix_sync(al[im], Al + (wm*32+im*16)*GS + st*16, GS);
            }
#pragma unroll
            for (int in=0;in<4;in++){
                BFragC bh_, bl_;
                wmma::load_matrix_sync(bh_, Bh + (wn*64+in*16)*GS + st*16, GS);
                wmma::load_matrix_sync(bl_, Bl + (wn*64+in*16)*GS + st*16, GS);
#pragma unroll
                for (int im=0;im<2;im++){
                    wmma::mma_sync(acc[im][in], ah[im], bh_, acc[im][in]);
                    wmma::mma_sync(acc[im][in], ah[im], bl_, acc[im][in]);
                    wmma::mma_sync(acc[im][in], al[im], bh_, acc[im][in]);
                }
            }
        }
        __syncthreads();
    }
#pragma unroll
    for (int im=0;im<2;im++)
#pragma unroll
      for (int in=0;in<4;in++)
        wmma::store_matrix_sync(&C[(size_t)(m0+wm*32+im*16)*Dc + n0+wn*64+in*16],
                                acc[im][in], Dc, wmma::mem_row_major);
}

// ---------------------------------------------------------------------------
// bias + xPos rotary + hi/lo split. Q pre-scaled by 1/32 (softmax scale).
// Reference swap handled by which biases the host passes.
// ---------------------------------------------------------------------------
__global__ __launch_bounds__(256) void rope_split_kernel(
    const float* __restrict__ Q, const float* __restrict__ K,
    const float* __restrict__ V,
    const float* __restrict__ bQ, const float* __restrict__ bK,
    const float* __restrict__ bV,
    __nv_bfloat16* __restrict__ Qh, __nv_bfloat16* __restrict__ Ql,
    __nv_bfloat16* __restrict__ Kh, __nv_bfloat16* __restrict__ Kl,
    __nv_bfloat16* __restrict__ Vh, __nv_bfloat16* __restrict__ Vl)
{
    int p = blockIdx.x*256 + threadIdx.x;     // p < NR*512
    int row = p >> 9;
    int col = (p & 511) << 1;
    int l = row & (Lc-1);
    int j = col & 63;
    float jf = (float)j;
    float inv_freq = powf(10000.0f, -jf * (1.0f/64.0f));
    float fr = (float)l * inv_freq;
    float sn, cs; sincosf(fr, &sn, &cs);
    float sv = (jf + 25.6f) * (1.0f/89.6f);
    float pw = ((float)l - 1024.0f) * (1.0f/512.0f);
    float sc = powf(sv, pw);
    float isc = 1.0f/sc;
    size_t base = (size_t)row*Dc + col;

    float q0 = Q[base] + bQ[col], q1 = Q[base+1] + bQ[col+1];
    float qo0 = (q0*cs - q1*sn) * sc * 0.03125f;
    float qo1 = (q1*cs + q0*sn) * sc * 0.03125f;
    uint32_t lo, hi;
    hi = pack2(qo0, qo1, lo);
    *(uint32_t*)(Qh + base) = hi;
    *(uint32_t*)(Ql + base) = lo;

    float k0 = K[base] + bK[col], k1 = K[base+1] + bK[col+1];
    float ko0 = (k0*cs - k1*sn) * isc;
    float ko1 = (k1*cs + k0*sn) * isc;
    hi = pack2(ko0, ko1, lo);
    *(uint32_t*)(Kh + base) = hi;
    *(uint32_t*)(Kl + base) = lo;

    float v0 = V[base] + bV[col], v1 = V[base+1] + bV[col+1];
    hi = pack2(v0, v1, lo);
    *(uint32_t*)(Vh + base) = hi;
    *(uint32_t*)(Vl + base) = lo;
}

// ---------------------------------------------------------------------------
// Single-pass FA2, pre-split bf16 inputs, cp.async K/V double-buffering.
// CTA: 128 q-rows x one (b,h); 8 warps x 16 rows; K/V tiles of 64 keys.
// Writes output as split bf16 (Th, Tl) for the output GEMM.
// ---------------------------------------------------------------------------
#define FSD 72
#define FSLICE (64*FSD)           // 4608 elems per 64x64 slice
#define FBUF (4*FSLICE)           // Kh,Kl,Vh,Vl per buffer = 18432 elems
#define FL_SMEM (2*FBUF*2)        // 73728 bytes

__global__ __launch_bounds__(256) void flash_kernel(
    const __nv_bfloat16* __restrict__ Qhg, const __nv_bfloat16* __restrict__ Qlg,
    const __nv_bfloat16* __restrict__ Khg, const __nv_bfloat16* __restrict__ Klg,
    const __nv_bfloat16* __restrict__ Vhg, const __nv_bfloat16* __restrict__ Vlg,
    __nv_bfloat16* __restrict__ Th, __nv_bfloat16* __restrict__ Tl)
{
    extern __shared__ __nv_bfloat16 smf[];
    uint32_t sbase = smem_u32(smf);

    const int tid = threadIdx.x;
    const int w = tid>>5, L = tid&31;
    const int lr = L&7, sel = (L>>3)&1;
    const int qt = blockIdx.x, bh = blockIdx.y;
    const int b = bh>>4, h = bh&15;
    const size_t qrow0 = (size_t)b*Lc + qt*128;
    const size_t krow0 = (size_t)b*Lc;

    // ---- stage Q (128x64, hi+lo) into smem via cp.async ----
#pragma unroll
    for (int i=0;i<8;i++){
        int sl = i>>2;                     // 0: Qh, 1: Ql
        int gg = tid + (i&3)*256;          // 0..1023
        int r = gg>>3, c8 = gg&7;
        const __nv_bfloat16* src = sl ? Qlg : Qhg;
        uint32_t so = sbase + (uint32_t)(sl*128*FSD + r*FSD + c8*8)*2;
        cpasync16(so, src + (qrow0 + r)*Dc + h*64 + c8*8);
    }
    CP_COMMIT(); CP_WAIT0();
    __syncthreads();

    // ---- Q fragments to registers ----
    uint32_t qh[4][4], ql[4][4];
    {
        int g = L>>3;
        int qrow = w*16 + (g&1)*8 + lr;
        int qcol = (g>>1)*8;
#pragma unroll
        for (int kk=0;kk<4;kk++){
            ldsm4(qh[kk], smem_u32(smf + qrow*FSD + kk*16 + qcol));
            ldsm4(ql[kk], smem_u32(smf + 128*FSD + qrow*FSD + kk*16 + qcol));
        }
    }
    __syncthreads();                       // Q smem free for K/V buffers

    float Oa[8][4];
#pragma unroll
    for (int n=0;n<8;n++){ Oa[n][0]=0.f; Oa[n][1]=0.f; Oa[n][2]=0.f; Oa[n][3]=0.f; }
    float m0r = -1e30f, m1r = -1e30f, l0r = 0.f, l1r = 0.f;

#define KV_LOAD(kt_, bsel) do { \
    _Pragma("unroll") \
    for (int i=0;i<8;i++){ \
        int sl = i>>1;                     /* 0:Kh 1:Kl 2:Vh 3:Vl */ \
        int gg = tid + (i&1)*256;          /* 0..511 */ \
        int r = gg>>3, c8 = gg&7; \
        const __nv_bfloat16* src = (sl==0)?Khg:(sl==1)?Klg:(sl==2)?Vhg:Vlg; \
        uint32_t so = sbase + (uint32_t)((bsel)*FBUF + sl*FSLICE + r*FSD + c8*8)*2; \
        cpasync16(so, src + (krow0 + (kt_)*64 + r)*Dc + h*64 + c8*8); \
    } } while(0)

    KV_LOAD(0, 0);
    CP_COMMIT();

    for (int kt=0; kt<Lc/64; kt++){
        if (kt < Lc/64 - 1){ KV_LOAD(kt+1, (kt+1)&1); CP_COMMIT(); CP_WAIT1(); }
        else CP_WAIT0();
        __syncthreads();

        const __nv_bfloat16* Khs = smf + (kt&1)*FBUF;
        const __nv_bfloat16* Kls = Khs + FSLICE;
        const __nv_bfloat16* Vhs = Khs + 2*FSLICE;
        const __nv_bfloat16* Vls = Khs + 3*FSLICE;

        // ---- S = Q K^T ----
        float S[8][4];
#pragma unroll
        for (int j=0;j<8;j++){ S[j][0]=0.f; S[j][1]=0.f; S[j][2]=0.f; S[j][3]=0.f; }
#pragma unroll
        for (int kk=0;kk<4;kk++){
#pragma unroll
            for (int j=0;j<8;j++){
                uint32_t kbh[2], kbl[2];
                uint32_t a = (uint32_t)((j*8 + lr)*FSD + kk*16 + sel*8);
                ldsm2(kbh, smem_u32(Khs + a));
                ldsm2(kbl, smem_u32(Kls + a));
                mma16816(S[j], qh[kk], kbh);
                mma16816(S[j], qh[kk], kbl);
                mma16816(S[j], ql[kk], kbh);
            }
        }

        // ---- online softmax ----
        float lm0 = -1e30f, lm1 = -1e30f;
#pragma unroll
        for (int j=0;j<8;j++){
            lm0 = fmaxf(lm0, fmaxf(S[j][0], S[j][1]));
            lm1 = fmaxf(lm1, fmaxf(S[j][2], S[j][3]));
        }
        lm0 = fmaxf(lm0, __shfl_xor_sync(0xffffffffu, lm0, 1));
        lm0 = fmaxf(lm0, __shfl_xor_sync(0xffffffffu, lm0, 2));
        lm1 = fmaxf(lm1, __shfl_xor_sync(0xffffffffu, lm1, 1));
        lm1 = fmaxf(lm1, __shfl_xor_sync(0xffffffffu, lm1, 2));
        float mn0 = fmaxf(m0r, lm0), mn1 = fmaxf(m1r, lm1);
        float al0 = __expf(m0r - mn0), al1 = __expf(m1r - mn1);
        m0r = mn0; m1r = mn1;
        l0r *= al0; l1r *= al1;
#pragma unroll
        for (int n=0;n<8;n++){
            Oa[n][0] *= al0; Oa[n][1] *= al0;
            Oa[n][2] *= al1; Oa[n][3] *= al1;
        }

        float s0 = 0.f, s1 = 0.f;
#pragma unroll
        for (int j=0;j<8;j++){
            S[j][0] = __expf(S[j][0] - mn0);
            S[j][1] = __expf(S[j][1] - mn0);
            S[j][2] = __expf(S[j][2] - mn1);
            S[j][3] = __expf(S[j][3] - mn1);
            s0 += S[j][0] + S[j][1];
            s1 += S[j][2] + S[j][3];
        }
        s0 += __shfl_xor_sync(0xffffffffu, s0, 1);
        s0 += __shfl_xor_sync(0xffffffffu, s0, 2);
        s1 += __shfl_xor_sync(0xffffffffu, s1, 1);
        s1 += __shfl_xor_sync(0xffffffffu, s1, 2);
        l0r += s0; l1r += s1;

        // ---- P: accumulator layout == A-operand layout, split hi/lo ----
        uint32_t ph[4][4], pl[4][4];
#pragma unroll
        for (int t=0;t<4;t++){
            ph[t][0] = pack2(S[2*t][0],   S[2*t][1],   pl[t][0]);
            ph[t][1] = pack2(S[2*t][2],   S[2*t][3],   pl[t][1]);
            ph[t][2] = pack2(S[2*t+1][0], S[2*t+1][1], pl[t][2]);
            ph[t][3] = pack2(S[2*t+1][2], S[2*t+1][3], pl[t][3]);
        }

        // ---- O += P V ----
#pragma unroll
        for (int t=0;t<4;t++){
#pragma unroll
            for (int n=0;n<8;n++){
                uint32_t vbh[2], vbl[2];
                uint32_t a = (uint32_t)((t*16 + sel*8 + lr)*FSD + n*8);
                ldsm2t(vbh, smem_u32(Vhs + a));
                ldsm2t(vbl, smem_u32(Vls + a));
                mma16816(Oa[n], ph[t], vbh);
                mma16816(Oa[n], ph[t], vbl);
                mma16816(Oa[n], pl[t], vbh);
            }
        }
        __syncthreads();
    }

    // ---- normalize + split-store O to (Th, Tl) ----
    float inv0 = 1.0f / l0r, inv1 = 1.0f / l1r;
    size_t row0 = qrow0 + w*16 + (L>>2);
    size_t row1 = row0 + 8;
    int colb = h*64 + 2*(L&3);
#pragma unroll
    for (int n=0;n<8;n++){
        uint32_t lo, hi;
        hi = pack2(Oa[n][0]*inv0, Oa[n][1]*inv0, lo);
        *(uint32_t*)(Th + row0*Dc + colb + n*8) = hi;
        *(uint32_t*)(Tl + row0*Dc + colb + n*8) = lo;
        hi = pack2(Oa[n][2]*inv1, Oa[n][3]*inv1, lo);
        *(uint32_t*)(Th + row1*Dc + colb + n*8) = hi;
        *(uint32_t*)(Tl + row1*Dc + colb + n*8) = lo;
    }
}

// ---------------------------------------------------------------------------
__global__ __launch_bounds__(256) void bias_add_kernel(
    float* __restrict__ out, const float* __restrict__ bias)
{
    int i = blockIdx.x*256 + threadIdx.x;
    float4 v = ((float4*)out)[i];
    int c = (i<<2) & (Dc-1);
    v.x += bias[c]; v.y += bias[c+1]; v.z += bias[c+2]; v.w += bias[c+3];
    ((float4*)out)[i] = v;
}

// ---------------------------------------------------------------------------
extern "C" void kernel_launch(void* const* d_in, const int* in_sizes, int n_in,
                              void* d_out, int out_size)
{
    const float* x  = (const float*)d_in[0];
    const float* Wq = (const float*)d_in[1];
    const float* bq = (const float*)d_in[2];
    const float* Wk = (const float*)d_in[3];
    const float* bk = (const float*)d_in[4];
    const float* Wv = (const float*)d_in[5];
    const float* bv = (const float*)d_in[6];
    const float* Wo = (const float*)d_in[7];
    const float* bo = (const float*)d_in[8];
    float* out = (float*)d_out;

    float *Qp, *Kp, *Vp;
    __nv_bfloat16 *xh, *xl, *Wh, *Wl, *Qh, *Ql, *Kh, *Kl, *Vh, *Vl, *Tph, *Tpl;
    cudaGetSymbolAddress((void**)&Qp, g_Q);
    cudaGetSymbolAddress((void**)&Kp, g_K);
    cudaGetSymbolAddress((void**)&Vp, g_V);
    cudaGetSymbolAddress((void**)&xh, g_xh);  cudaGetSymbolAddress((void**)&xl, g_xl);
    cudaGetSymbolAddress((void**)&Wh, g_Wh);  cudaGetSymbolAddress((void**)&Wl, g_Wl);
    cudaGetSymbolAddress((void**)&Qh, g_Qh);  cudaGetSymbolAddress((void**)&Ql, g_Ql);
    cudaGetSymbolAddress((void**)&Kh, g_Kh);  cudaGetSymbolAddress((void**)&Kl, g_Kl);
    cudaGetSymbolAddress((void**)&Vh, g_Vh);  cudaGetSymbolAddress((void**)&Vl, g_Vl);
    cudaGetSymbolAddress((void**)&Tph, g_Th); cudaGetSymbolAddress((void**)&Tpl, g_Tl);

    cudaFuncSetAttribute(gemm_split, cudaFuncAttributeMaxDynamicSharedMemorySize, G_SMEM);
    cudaFuncSetAttribute(flash_kernel, cudaFuncAttributeMaxDynamicSharedMemorySize, FL_SMEM);

    // ---- pre-split x and weights (slots: 0=Wq, 1=Wv(->K), 2=Wk(->V), 3=Wo) ----
    split_kernel<<<(NR*Dc/4)/256, 256>>>(x,  xh, xl);
    split_kernel<<<(DD/4)/256, 256>>>(Wq, Wh + 0*DD, Wl + 0*DD);
    split_kernel<<<(DD/4)/256, 256>>>(Wv, Wh + 1*DD, Wl + 1*DD);
    split_kernel<<<(DD/4)/256, 256>>>(Wk, Wh + 2*DD, Wl + 2*DD);
    split_kernel<<<(DD/4)/256, 256>>>(Wo, Wh + 3*DD, Wl + 3*DD);

    dim3 ggrid(Dc/128, NR/128);   // (8, 32)

    // ---- projections (f32 out; biases added in rope kernel) ----
    gemm_split<<<ggrid, 256, G_SMEM>>>(xh, xl, Wh + 0*DD, Wl + 0*DD, Qp);
    gemm_split<<<ggrid, 256, G_SMEM>>>(xh, xl, Wh + 1*DD, Wl + 1*DD, Kp);
    gemm_split<<<ggrid, 256, G_SMEM>>>(xh, xl, Wh + 2*DD, Wl + 2*DD, Vp);

    // ---- bias + xPos + split (Q uses bq, K uses bv, V uses bk) ----
    rope_split_kernel<<<(NR*512)/256, 256>>>(Qp, Kp, Vp, bq, bv, bk,
                                             Qh, Ql, Kh, Kl, Vh, Vl);

    // ---- single-pass flash attention ----
    flash_kernel<<<dim3(Lc/128, Bc*16), 256, FL_SMEM>>>(Qh, Ql, Kh, Kl, Vh, Vl,
                                                        Tph, Tpl);

    // ---- output projection + bias ----
    gemm_split<<<ggrid, 256, G_SMEM>>>(Tph, Tpl, Wh + 3*DD, Wl + 3*DD, out);
    bias_add_kernel<<<(NR*Dc/4)/256, 256>>>(out, bo);
}

// round 12
// speedup vs baseline: 4.1866x; 1.2973x over previous
#include <cuda_runtime.h>
#include <cuda_bf16.h>
#include <mma.h>
#include <math.h>
#include <stdint.h>

using namespace nvcuda;

#define Bc 2
#define Lc 2048
#define Dc 1024
#define NR (Bc*Lc)
#define DD (Dc*Dc)

// pre-split bf16 operands
__device__ __nv_bfloat16 g_xh[NR*Dc], g_xl[NR*Dc];
__device__ __nv_bfloat16 g_Wh[4*DD],  g_Wl[4*DD];
__device__ __nv_bfloat16 g_Qh[NR*Dc], g_Ql[NR*Dc];
__device__ __nv_bfloat16 g_Kh[NR*Dc], g_Kl[NR*Dc];
__device__ __nv_bfloat16 g_Vh[NR*Dc], g_Vl[NR*Dc];
__device__ __nv_bfloat16 g_Th[NR*Dc], g_Tl[NR*Dc];

// ---------------------------------------------------------------------------
// helpers
// ---------------------------------------------------------------------------
__device__ __forceinline__ uint32_t smem_u32(const void* p){
    uint32_t a;
    asm("{ .reg .u64 t; cvta.to.shared.u64 t, %1; cvt.u32.u64 %0, t; }"
        : "=r"(a) : "l"(p));
    return a;
}
__device__ __forceinline__ float fexp2(float x){
    float y; asm("ex2.approx.f32 %0, %1;" : "=f"(y) : "f"(x)); return y;
}
__device__ __forceinline__ float flog2(float x){
    float y; asm("lg2.approx.f32 %0, %1;" : "=f"(y) : "f"(x)); return y;
}
__device__ __forceinline__ uint32_t pack2(float a, float b, uint32_t& lo){
    __nv_bfloat16 ha = __float2bfloat16(a), hb = __float2bfloat16(b);
    __nv_bfloat16 la = __float2bfloat16(a - __bfloat162float(ha));
    __nv_bfloat16 lb = __float2bfloat16(b - __bfloat162float(hb));
    lo = (uint32_t)__bfloat16_as_ushort(la) | ((uint32_t)__bfloat16_as_ushort(lb)<<16);
    return (uint32_t)__bfloat16_as_ushort(ha) | ((uint32_t)__bfloat16_as_ushort(hb)<<16);
}
__device__ __forceinline__ void store_split4(void* ph, void* pl, float4 v){
    uint2 H, L;
    H.x = pack2(v.x, v.y, L.x);
    H.y = pack2(v.z, v.w, L.y);
    *(uint2*)ph = H;
    *(uint2*)pl = L;
}
__device__ __forceinline__ void cpasync16(uint32_t saddr, const void* g){
    asm volatile("cp.async.ca.shared.global [%0], [%1], 16;" :: "r"(saddr), "l"(g));
}
#define CP_COMMIT() asm volatile("cp.async.commit_group;" ::: "memory")
#define CP_WAIT1()  asm volatile("cp.async.wait_group 1;" ::: "memory")
#define CP_WAIT0()  asm volatile("cp.async.wait_group 0;" ::: "memory")

__device__ __forceinline__ void mma16816(float* d, const uint32_t* a, const uint32_t* b){
    asm volatile(
        "mma.sync.aligned.m16n8k16.row.col.f32.bf16.bf16.f32 "
        "{%0,%1,%2,%3}, {%4,%5,%6,%7}, {%8,%9}, {%0,%1,%2,%3};"
        : "+f"(d[0]), "+f"(d[1]), "+f"(d[2]), "+f"(d[3])
        : "r"(a[0]), "r"(a[1]), "r"(a[2]), "r"(a[3]), "r"(b[0]), "r"(b[1]));
}
__device__ __forceinline__ void ldsm4(uint32_t* r, uint32_t addr){
    asm volatile("ldmatrix.sync.aligned.m8n8.x4.shared.b16 {%0,%1,%2,%3}, [%4];"
        : "=r"(r[0]), "=r"(r[1]), "=r"(r[2]), "=r"(r[3]) : "r"(addr));
}
__device__ __forceinline__ void ldsm4t(uint32_t* r, uint32_t addr){
    asm volatile("ldmatrix.sync.aligned.m8n8.x4.trans.shared.b16 {%0,%1,%2,%3}, [%4];"
        : "=r"(r[0]), "=r"(r[1]), "=r"(r[2]), "=r"(r[3]) : "r"(addr));
}

typedef wmma::fragment<wmma::matrix_a,16,16,16,__nv_bfloat16,wmma::row_major> AFrag;
typedef wmma::fragment<wmma::matrix_b,16,16,16,__nv_bfloat16,wmma::col_major> BFragC;
typedef wmma::fragment<wmma::accumulator,16,16,16,float> CFrag;

// ---------------------------------------------------------------------------
// split kernels
// ---------------------------------------------------------------------------
__global__ __launch_bounds__(256) void split_x_kernel(
    const float* __restrict__ in, __nv_bfloat16* __restrict__ hi,
    __nv_bfloat16* __restrict__ lo)
{
    int i = blockIdx.x*256 + threadIdx.x;
    float4 v = ((const float4*)in)[i];
    store_split4(hi + 4*(size_t)i, lo + 4*(size_t)i, v);
}
// All four weights in one launch. Slot order: 0=Wq, 1=Wv(->K), 2=Wk(->V), 3=Wo
__global__ __launch_bounds__(256) void split_w_kernel(
    const float* __restrict__ Wq, const float* __restrict__ Wv,
    const float* __restrict__ Wk, const float* __restrict__ Wo,
    __nv_bfloat16* __restrict__ hi, __nv_bfloat16* __restrict__ lo)
{
    int slot = blockIdx.x >> 10;
    const float* src = slot==0 ? Wq : slot==1 ? Wv : slot==2 ? Wk : Wo;
    int i = (blockIdx.x & 1023)*256 + threadIdx.x;     // < DD/4
    float4 v = ((const float4*)src)[i];
    size_t o = (size_t)slot*DD + 4*(size_t)i;
    store_split4(hi + o, lo + o, v);
}

// ---------------------------------------------------------------------------
// GEMM mainloop core: acc[2][4] += A[128xK] @ W[128xK]^T over K=1024,
// operands pre-split bf16, cp.async double-buffered, 3-mma split.
// ---------------------------------------------------------------------------
#define GS 40
#define GMAT (128*GS)
#define G_SMEM (2*4*GMAT*2)       // 81920 bytes

__device__ __forceinline__ void gemm_core(
    const __nv_bfloat16* __restrict__ Agh, const __nv_bfloat16* __restrict__ Agl,
    const __nv_bfloat16* __restrict__ Bgh, const __nv_bfloat16* __restrict__ Bgl,
    __nv_bfloat16* sm, uint32_t sbase, int tid, int wm, int wn,
    int m0, int n0, CFrag (&acc)[2][4])
{
#define G_LOAD(k0, bsel) do { \
    uint32_t s0 = sbase + (uint32_t)((bsel)*4*GMAT)*2; \
    _Pragma("unroll") \
    for (int i=0;i<2;i++){ \
        int g = tid + i*256; \
        int r = g>>2, c8 = g&3; \
        uint32_t so = s0 + (uint32_t)(r*GS + c8*8)*2; \
        size_t ga = (size_t)(m0+r)*Dc + (k0) + c8*8; \
        size_t gb = (size_t)(n0+r)*Dc + (k0) + c8*8; \
        cpasync16(so,              Agh + ga); \
        cpasync16(so + 2*GMAT,     Agl + ga); \
        cpasync16(so + 4*GMAT,     Bgh + gb); \
        cpasync16(so + 6*GMAT,     Bgl + gb); \
    } } while(0)

    G_LOAD(0, 0);
    CP_COMMIT();

    for (int ch=0; ch<32; ch++){
        if (ch < 31){ G_LOAD((ch+1)*32, (ch+1)&1); CP_COMMIT(); CP_WAIT1(); }
        else CP_WAIT0();
        __syncthreads();

        const __nv_bfloat16* Ah = sm + (ch&1)*4*GMAT;
        const __nv_bfloat16* Al = Ah + GMAT;
        const __nv_bfloat16* Bh = Ah + 2*GMAT;
        const __nv_bfloat16* Bl = Ah + 3*GMAT;
#pragma unroll
        for (int st=0; st<2; st++){
            AFrag ah[2], al[2];
#pragma unroll
            for (int im=0;im<2;im++){
                wmma::load_matrix_sync(ah[im], Ah + (wm*32+im*16)*GS + st*16, GS);
                wmma::load_matrix_sync(al[im], Al + (wm*32+im*16)*GS + st*16, GS);
            }
#pragma unroll
            for (int in=0;in<4;in++){
                BFragC bh_, bl_;
                wmma::load_matrix_sync(bh_, Bh + (wn*64+in*16)*GS + st*16, GS);
                wmma::load_matrix_sync(bl_, Bl + (wn*64+in*16)*GS + st*16, GS);
#pragma unroll
                for (int im=0;im<2;im++){
                    wmma::mma_sync(acc[im][in], ah[im], bh_, acc[im][in]);
                    wmma::mma_sync(acc[im][in], ah[im], bl_, acc[im][in]);
                    wmma::mma_sync(acc[im][in], al[im], bh_, acc[im][in]);
                }
            }
        }
        __syncthreads();
    }
#undef G_LOAD
}

// ---------------------------------------------------------------------------
// Fused projection GEMM: grid (24, 32). slot = blockIdx.x>>3 selects weight.
// Epilogue: bias + xPos rotary (Q: *sc*log2e/32, K: /sc, V: bias only)
// + hi/lo split, written straight to split-bf16 buffers.
// ---------------------------------------------------------------------------
#define STS 132                    // f32 staging stride

__global__ __launch_bounds__(256) void gemm_proj(
    const __nv_bfloat16* __restrict__ Agh, const __nv_bfloat16* __restrict__ Agl,
    const __nv_bfloat16* __restrict__ Wh,  const __nv_bfloat16* __restrict__ Wl,
    const float* __restrict__ bq, const float* __restrict__ bv,
    const float* __restrict__ bk,
    __nv_bfloat16* __restrict__ Qh, __nv_bfloat16* __restrict__ Ql,
    __nv_bfloat16* __restrict__ Kh, __nv_bfloat16* __restrict__ Kl,
    __nv_bfloat16* __restrict__ Vh, __nv_bfloat16* __restrict__ Vl)
{
    extern __shared__ __nv_bfloat16 sm[];
    uint32_t sbase = smem_u32(sm);
    const int tid = threadIdx.x, wid = tid>>5;
    const int wm = wid>>1, wn = wid&1;
    const int slot = blockIdx.x>>3;
    const int m0 = blockIdx.y*128, n0 = (blockIdx.x&7)*128;

    CFrag acc[2][4];
#pragma unroll
    for (int i=0;i<2;i++)
#pragma unroll
      for (int j=0;j<4;j++) wmma::fill_fragment(acc[i][j], 0.0f);

    gemm_core(Agh, Agl, Wh + (size_t)slot*DD, Wl + (size_t)slot*DD,
              sm, sbase, tid, wm, wn, m0, n0, acc);

    // ---- stage accumulators in smem ----
    float* stf = (float*)sm;
#pragma unroll
    for (int im=0;im<2;im++)
#pragma unroll
      for (int in=0;in<4;in++)
        wmma::store_matrix_sync(&stf[(wm*32+im*16)*STS + wn*64+in*16],
                                acc[im][in], STS, wmma::mem_row_major);
    __syncthreads();

    // ---- epilogue: bias + rope + split ----
    const float* bias = slot==0 ? bq : slot==1 ? bv : bk;
    __nv_bfloat16* Dh = slot==0 ? Qh : slot==1 ? Kh : Vh;
    __nv_bfloat16* Dl = slot==0 ? Ql : slot==1 ? Kl : Vl;
#pragma unroll
    for (int i=0;i<32;i++){
        int idx = tid + i*256;            // 8192 pairs in 128x128 tile
        int r = idx>>6, cp = idx&63;
        int cc = n0 + 2*cp;
        float a  = stf[r*STS + 2*cp]     + bias[cc];
        float b2 = stf[r*STS + 2*cp + 1] + bias[cc+1];
        float o0, o1;
        if (slot == 2){
            o0 = a; o1 = b2;
        } else {
            int m = m0 + r, l = m & (Lc-1), j = cc & 63;
            float jf = (float)j;
            // 10000^(-j/64) = exp2(-j/64 * log2(10000))
            float fr = (float)l * fexp2(jf * (-13.287712379549449f/64.0f));
            float sn, cs; sincosf(fr, &sn, &cs);
            float sv = (jf + 25.6f) * (1.0f/89.6f);
            float pw = ((float)l - 1024.0f) * (1.0f/512.0f);
            float sc = fexp2(pw * flog2(sv));
            float s = (slot==0) ? sc * (0.03125f * 1.4426950408889634f)
                                : 1.0f/sc;
            o0 = (a*cs - b2*sn) * s;
            o1 = (b2*cs + a*sn) * s;
        }
        uint32_t lo, hi = pack2(o0, o1, lo);
        size_t base = (size_t)(m0 + r)*Dc + cc;
        *(uint32_t*)(Dh + base) = hi;
        *(uint32_t*)(Dl + base) = lo;
    }
}

// ---------------------------------------------------------------------------
// Output GEMM: out = T @ Wo^T + bo (f32 out, bias fused)
// ---------------------------------------------------------------------------
__global__ __launch_bounds__(256) void gemm_out(
    const __nv_bfloat16* __restrict__ Agh, const __nv_bfloat16* __restrict__ Agl,
    const __nv_bfloat16* __restrict__ Wh,  const __nv_bfloat16* __restrict__ Wl,
    const float* __restrict__ bo, float* __restrict__ out)
{
    extern __shared__ __nv_bfloat16 sm[];
    uint32_t sbase = smem_u32(sm);
    const int tid = threadIdx.x, wid = tid>>5;
    const int wm = wid>>1, wn = wid&1;
    const int m0 = blockIdx.y*128, n0 = blockIdx.x*128;

    CFrag acc[2][4];
#pragma unroll
    for (int i=0;i<2;i++)
#pragma unroll
      for (int j=0;j<4;j++) wmma::fill_fragment(acc[i][j], 0.0f);

    gemm_core(Agh, Agl, Wh, Wl, sm, sbase, tid, wm, wn, m0, n0, acc);

    float* stf = (float*)sm;
#pragma unroll
    for (int im=0;im<2;im++)
#pragma unroll
      for (int in=0;in<4;in++)
        wmma::store_matrix_sync(&stf[(wm*32+im*16)*STS + wn*64+in*16],
                                acc[im][in], STS, wmma::mem_row_major);
    __syncthreads();

#pragma unroll
    for (int i=0;i<16;i++){
        int idx = tid + i*256;            // 4096 float4-groups
        int r = idx>>5, c4 = (idx&31)<<2;
        float4 v;
        v.x = stf[r*STS + c4]     + bo[n0+c4];
        v.y = stf[r*STS + c4 + 1] + bo[n0+c4+1];
        v.z = stf[r*STS + c4 + 2] + bo[n0+c4+2];
        v.w = stf[r*STS + c4 + 3] + bo[n0+c4+3];
        *(float4*)&out[(size_t)(m0+r)*Dc + n0 + c4] = v;
    }
}

// ---------------------------------------------------------------------------
// Single-pass FA2, pre-split bf16 inputs (Q pre-scaled by log2e/32 upstream),
// cp.async K/V double-buffering, ldsm.x4 operand loads, exp2 softmax.
// CTA: 128 q-rows x one (b,h); 8 warps x 16 rows; K/V tiles of 64 keys.
// ---------------------------------------------------------------------------
#define FSD 72
#define FSLICE (64*FSD)
#define FBUF (4*FSLICE)
#define FL_SMEM (2*FBUF*2)        // 73728 bytes

__global__ __launch_bounds__(256) void flash_kernel(
    const __nv_bfloat16* __restrict__ Qhg, const __nv_bfloat16* __restrict__ Qlg,
    const __nv_bfloat16* __restrict__ Khg, const __nv_bfloat16* __restrict__ Klg,
    const __nv_bfloat16* __restrict__ Vhg, const __nv_bfloat16* __restrict__ Vlg,
    __nv_bfloat16* __restrict__ Th, __nv_bfloat16* __restrict__ Tl)
{
    extern __shared__ __nv_bfloat16 smf[];
    uint32_t sbase = smem_u32(smf);

    const int tid = threadIdx.x;
    const int w = tid>>5, L = tid&31;
    const int lr = L&7;
    const int qt = blockIdx.x, bh = blockIdx.y;
    const int b = bh>>4, h = bh&15;
    const size_t qrow0 = (size_t)b*Lc + qt*128;
    const size_t krow0 = (size_t)b*Lc;

    // ---- stage Q (128x64, hi+lo) into smem via cp.async ----
#pragma unroll
    for (int i=0;i<8;i++){
        int sl = i>>2;
        int gg = tid + (i&3)*256;
        int r = gg>>3, c8 = gg&7;
        const __nv_bfloat16* src = sl ? Qlg : Qhg;
        uint32_t so = sbase + (uint32_t)(sl*128*FSD + r*FSD + c8*8)*2;
        cpasync16(so, src + (qrow0 + r)*Dc + h*64 + c8*8);
    }
    CP_COMMIT(); CP_WAIT0();
    __syncthreads();

    // ---- Q fragments to registers ----
    uint32_t qh[4][4], ql[4][4];
    {
        int g = L>>3;
        int qrow = w*16 + (g&1)*8 + lr;
        int qcol = (g>>1)*8;
#pragma unroll
        for (int kk=0;kk<4;kk++){
            ldsm4(qh[kk], smem_u32(smf + qrow*FSD + kk*16 + qcol));
            ldsm4(ql[kk], smem_u32(smf + 128*FSD + qrow*FSD + kk*16 + qcol));
        }
    }
    __syncthreads();

    float Oa[8][4];
#pragma unroll
    for (int n=0;n<8;n++){ Oa[n][0]=0.f; Oa[n][1]=0.f; Oa[n][2]=0.f; Oa[n][3]=0.f; }
    float m0r = -1e30f, m1r = -1e30f, l0r = 0.f, l1r = 0.f;

    // ldsm.x4 per-lane address bases
    const uint32_t krow_base = ((L>>4)<<3) + lr;       // K: j-pair rows
    const uint32_t kcol_base = ((L>>3)&1)<<3;
    const uint32_t vrow_base = (((L>>3)&1)<<3) + lr;   // V: k-rows (trans)
    const uint32_t vcol_base = (L>>4)<<3;

#define KV_LOAD(kt_, bsel) do { \
    _Pragma("unroll") \
    for (int i=0;i<8;i++){ \
        int sl = i>>1; \
        int gg = tid + (i&1)*256; \
        int r = gg>>3, c8 = gg&7; \
        const __nv_bfloat16* src = (sl==0)?Khg:(sl==1)?Klg:(sl==2)?Vhg:Vlg; \
        uint32_t so = sbase + (uint32_t)((bsel)*FBUF + sl*FSLICE + r*FSD + c8*8)*2; \
        cpasync16(so, src + (krow0 + (kt_)*64 + r)*Dc + h*64 + c8*8); \
    } } while(0)

    KV_LOAD(0, 0);
    CP_COMMIT();

    for (int kt=0; kt<Lc/64; kt++){
        if (kt < Lc/64 - 1){ KV_LOAD(kt+1, (kt+1)&1); CP_COMMIT(); CP_WAIT1(); }
        else CP_WAIT0();
        __syncthreads();

        const __nv_bfloat16* Khs = smf + (kt&1)*FBUF;
        const __nv_bfloat16* Kls = Khs + FSLICE;
        const __nv_bfloat16* Vhs = Khs + 2*FSLICE;
        const __nv_bfloat16* Vls = Khs + 3*FSLICE;

        // ---- S = Q K^T (log2 domain; Q carries log2e/32) ----
        float S[8][4];
#pragma unroll
        for (int j=0;j<8;j++){ S[j][0]=0.f; S[j][1]=0.f; S[j][2]=0.f; S[j][3]=0.f; }
#pragma unroll
        for (int kk=0;kk<4;kk++){
#pragma unroll
            for (int jp=0;jp<4;jp++){
                uint32_t kh4[4], kl4[4];
                uint32_t a = (uint32_t)((jp*16 + krow_base)*FSD + kk*16 + kcol_base);
                ldsm4(kh4, smem_u32(Khs + a));
                ldsm4(kl4, smem_u32(Kls + a));
                mma16816(S[2*jp],   qh[kk], kh4);
                mma16816(S[2*jp],   qh[kk], kl4);
                mma16816(S[2*jp],   ql[kk], kh4);
                mma16816(S[2*jp+1], qh[kk], kh4+2);
                mma16816(S[2*jp+1], qh[kk], kl4+2);
                mma16816(S[2*jp+1], ql[kk], kh4+2);
            }
        }

        // ---- online softmax (exp2) ----
        float lm0 = -1e30f, lm1 = -1e30f;
#pragma unroll
        for (int j=0;j<8;j++){
            lm0 = fmaxf(lm0, fmaxf(S[j][0], S[j][1]));
            lm1 = fmaxf(lm1, fmaxf(S[j][2], S[j][3]));
        }
        lm0 = fmaxf(lm0, __shfl_xor_sync(0xffffffffu, lm0, 1));
        lm0 = fmaxf(lm0, __shfl_xor_sync(0xffffffffu, lm0, 2));
        lm1 = fmaxf(lm1, __shfl_xor_sync(0xffffffffu, lm1, 1));
        lm1 = fmaxf(lm1, __shfl_xor_sync(0xffffffffu, lm1, 2));
        float mn0 = fmaxf(m0r, lm0), mn1 = fmaxf(m1r, lm1);
        float al0 = fexp2(m0r - mn0), al1 = fexp2(m1r - mn1);
        m0r = mn0; m1r = mn1;
        l0r *= al0; l1r *= al1;
#pragma unroll
        for (int n=0;n<8;n++){
            Oa[n][0] *= al0; Oa[n][1] *= al0;
            Oa[n][2] *= al1; Oa[n][3] *= al1;
        }

        float s0 = 0.f, s1 = 0.f;
#pragma unroll
        for (int j=0;j<8;j++){
            S[j][0] = fexp2(S[j][0] - mn0);
            S[j][1] = fexp2(S[j][1] - mn0);
            S[j][2] = fexp2(S[j][2] - mn1);
            S[j][3] = fexp2(S[j][3] - mn1);
            s0 += S[j][0] + S[j][1];
            s1 += S[j][2] + S[j][3];
        }
        s0 += __shfl_xor_sync(0xffffffffu, s0, 1);
        s0 += __shfl_xor_sync(0xffffffffu, s0, 2);
        s1 += __shfl_xor_sync(0xffffffffu, s1, 1);
        s1 += __shfl_xor_sync(0xffffffffu, s1, 2);
        l0r += s0; l1r += s1;

        // ---- P: accumulator layout == A-operand layout, split hi/lo ----
        uint32_t ph[4][4], pl[4][4];
#pragma unroll
        for (int t=0;t<4;t++){
            ph[t][0] = pack2(S[2*t][0],   S[2*t][1],   pl[t][0]);
            ph[t][1] = pack2(S[2*t][2],   S[2*t][3],   pl[t][1]);
            ph[t][2] = pack2(S[2*t+1][0], S[2*t+1][1], pl[t][2]);
            ph[t][3] = pack2(S[2*t+1][2], S[2*t+1][3], pl[t][3]);
        }

        // ---- O += P V ----
#pragma unroll
        for (int t=0;t<4;t++){
#pragma unroll
            for (int np=0;np<4;np++){
                uint32_t vh4[4], vl4[4];
                uint32_t a = (uint32_t)((t*16 + vrow_base)*FSD + np*16 + vcol_base);
                ldsm4t(vh4, smem_u32(Vhs + a));
                ldsm4t(vl4, smem_u32(Vls + a));
                mma16816(Oa[2*np],   ph[t], vh4);
                mma16816(Oa[2*np],   ph[t], vl4);
                mma16816(Oa[2*np],   pl[t], vh4);
                mma16816(Oa[2*np+1], ph[t], vh4+2);
                mma16816(Oa[2*np+1], ph[t], vl4+2);
                mma16816(Oa[2*np+1], pl[t], vh4+2);
            }
        }
        __syncthreads();
    }

    // ---- normalize + split-store O ----
    float inv0 = 1.0f / l0r, inv1 = 1.0f / l1r;
    size_t row0 = qrow0 + w*16 + (L>>2);
    size_t row1 = row0 + 8;
    int colb = h*64 + 2*(L&3);
#pragma unroll
    for (int n=0;n<8;n++){
        uint32_t lo, hi;
        hi = pack2(Oa[n][0]*inv0, Oa[n][1]*inv0, lo);
        *(uint32_t*)(Th + row0*Dc + colb + n*8) = hi;
        *(uint32_t*)(Tl + row0*Dc + colb + n*8) = lo;
        hi = pack2(Oa[n][2]*inv1, Oa[n][3]*inv1, lo);
        *(uint32_t*)(Th + row1*Dc + colb + n*8) = hi;
        *(uint32_t*)(Tl + row1*Dc + colb + n*8) = lo;
    }
}

// ---------------------------------------------------------------------------
extern "C" void kernel_launch(void* const* d_in, const int* in_sizes, int n_in,
                              void* d_out, int out_size)
{
    const float* x  = (const float*)d_in[0];
    const float* Wq = (const float*)d_in[1];
    const float* bq = (const float*)d_in[2];
    const float* Wk = (const float*)d_in[3];
    const float* bk = (const float*)d_in[4];
    const float* Wv = (const float*)d_in[5];
    const float* bv = (const float*)d_in[6];
    const float* Wo = (const float*)d_in[7];
    const float* bo = (const float*)d_in[8];
    float* out = (float*)d_out;

    __nv_bfloat16 *xh, *xl, *Wh, *Wl, *Qh, *Ql, *Kh, *Kl, *Vh, *Vl, *Tph, *Tpl;
    cudaGetSymbolAddress((void**)&xh, g_xh);  cudaGetSymbolAddress((void**)&xl, g_xl);
    cudaGetSymbolAddress((void**)&Wh, g_Wh);  cudaGetSymbolAddress((void**)&Wl, g_Wl);
    cudaGetSymbolAddress((void**)&Qh, g_Qh);  cudaGetSymbolAddress((void**)&Ql, g_Ql);
    cudaGetSymbolAddress((void**)&Kh, g_Kh);  cudaGetSymbolAddress((void**)&Kl, g_Kl);
    cudaGetSymbolAddress((void**)&Vh, g_Vh);  cudaGetSymbolAddress((void**)&Vl, g_Vl);
    cudaGetSymbolAddress((void**)&Tph, g_Th); cudaGetSymbolAddress((void**)&Tpl, g_Tl);

    cudaFuncSetAttribute(gemm_proj, cudaFuncAttributeMaxDynamicSharedMemorySize, G_SMEM);
    cudaFuncSetAttribute(gemm_out,  cudaFuncAttributeMaxDynamicSharedMemorySize, G_SMEM);
    cudaFuncSetAttribute(flash_kernel, cudaFuncAttributeMaxDynamicSharedMemorySize, FL_SMEM);

    // ---- pre-split x and all weights (2 launches) ----
    split_x_kernel<<<(NR*Dc/4)/256, 256>>>(x, xh, xl);
    split_w_kernel<<<4*(DD/4)/256, 256>>>(Wq, Wv, Wk, Wo, Wh, Wl);

    // ---- merged projections + fused bias/rope/split epilogue ----
    gemm_proj<<<dim3(24, NR/128), 256, G_SMEM>>>(xh, xl, Wh, Wl,
                                                 bq, bv, bk,
                                                 Qh, Ql, Kh, Kl, Vh, Vl);

    // ---- single-pass flash attention ----
    flash_kernel<<<dim3(Lc/128, Bc*16), 256, FL_SMEM>>>(Qh, Ql, Kh, Kl, Vh, Vl,
                                                        Tph, Tpl);

    // ---- output projection + fused bias ----
    gemm_out<<<dim3(Dc/128, NR/128), 256, G_SMEM>>>(Tph, Tpl, Wh + 3*(size_t)DD,
                                                    Wl + 3*(size_t)DD, bo, out);
}

// round 13
// speedup vs baseline: 4.5996x; 1.0986x over previous
#include <cuda_runtime.h>
#include <cuda_bf16.h>
#include <cuda_fp16.h>
#include <mma.h>
#include <math.h>
#include <stdint.h>

using namespace nvcuda;

#define Bc 2
#define Lc 2048
#define Dc 1024
#define NR (Bc*Lc)
#define DD (Dc*Dc)

// pre-split bf16 operands (GEMM inputs)
__device__ __nv_bfloat16 g_xh[NR*Dc], g_xl[NR*Dc];
__device__ __nv_bfloat16 g_Wh[4*DD],  g_Wl[4*DD];
// fp16 flash operands (Q hi/lo, K single, V single)
__device__ __half g_Qh[NR*Dc], g_Ql[NR*Dc];
__device__ __half g_Kh[NR*Dc];
__device__ __half g_Vh[NR*Dc];
// flash output, split bf16 for output GEMM
__device__ __nv_bfloat16 g_Th[NR*Dc], g_Tl[NR*Dc];

// ---------------------------------------------------------------------------
// helpers
// ---------------------------------------------------------------------------
__device__ __forceinline__ uint32_t smem_u32(const void* p){
    uint32_t a;
    asm("{ .reg .u64 t; cvta.to.shared.u64 t, %1; cvt.u32.u64 %0, t; }"
        : "=r"(a) : "l"(p));
    return a;
}
__device__ __forceinline__ float fexp2(float x){
    float y; asm("ex2.approx.f32 %0, %1;" : "=f"(y) : "f"(x)); return y;
}
// bf16 hi/lo split pack
__device__ __forceinline__ uint32_t pack2(float a, float b, uint32_t& lo){
    __nv_bfloat16 ha = __float2bfloat16(a), hb = __float2bfloat16(b);
    __nv_bfloat16 la = __float2bfloat16(a - __bfloat162float(ha));
    __nv_bfloat16 lb = __float2bfloat16(b - __bfloat162float(hb));
    lo = (uint32_t)__bfloat16_as_ushort(la) | ((uint32_t)__bfloat16_as_ushort(lb)<<16);
    return (uint32_t)__bfloat16_as_ushort(ha) | ((uint32_t)__bfloat16_as_ushort(hb)<<16);
}
__device__ __forceinline__ void store_split4(void* ph, void* pl, float4 v){
    uint2 H, L;
    H.x = pack2(v.x, v.y, L.x);
    H.y = pack2(v.z, v.w, L.y);
    *(uint2*)ph = H;
    *(uint2*)pl = L;
}
// fp16 hi/lo split pack
__device__ __forceinline__ uint32_t pack2h(float a, float b, uint32_t& lo){
    __half ha = __float2half(a), hb = __float2half(b);
    __half la = __float2half(a - __half2float(ha));
    __half lb = __float2half(b - __half2float(hb));
    lo = (uint32_t)__half_as_ushort(la) | ((uint32_t)__half_as_ushort(lb)<<16);
    return (uint32_t)__half_as_ushort(ha) | ((uint32_t)__half_as_ushort(hb)<<16);
}
__device__ __forceinline__ uint32_t pack2h_single(float a, float b){
    __half ha = __float2half(a), hb = __float2half(b);
    return (uint32_t)__half_as_ushort(ha) | ((uint32_t)__half_as_ushort(hb)<<16);
}
__device__ __forceinline__ void cpasync16(uint32_t saddr, const void* g){
    asm volatile("cp.async.ca.shared.global [%0], [%1], 16;" :: "r"(saddr), "l"(g));
}
#define CP_COMMIT() asm volatile("cp.async.commit_group;" ::: "memory")
#define CP_WAIT1()  asm volatile("cp.async.wait_group 1;" ::: "memory")
#define CP_WAIT0()  asm volatile("cp.async.wait_group 0;" ::: "memory")

__device__ __forceinline__ void mma16816(float* d, const uint32_t* a, const uint32_t* b){
    asm volatile(
        "mma.sync.aligned.m16n8k16.row.col.f32.bf16.bf16.f32 "
        "{%0,%1,%2,%3}, {%4,%5,%6,%7}, {%8,%9}, {%0,%1,%2,%3};"
        : "+f"(d[0]), "+f"(d[1]), "+f"(d[2]), "+f"(d[3])
        : "r"(a[0]), "r"(a[1]), "r"(a[2]), "r"(a[3]), "r"(b[0]), "r"(b[1]));
}
__device__ __forceinline__ void mma16816h(float* d, const uint32_t* a, const uint32_t* b){
    asm volatile(
        "mma.sync.aligned.m16n8k16.row.col.f32.f16.f16.f32 "
        "{%0,%1,%2,%3}, {%4,%5,%6,%7}, {%8,%9}, {%0,%1,%2,%3};"
        : "+f"(d[0]), "+f"(d[1]), "+f"(d[2]), "+f"(d[3])
        : "r"(a[0]), "r"(a[1]), "r"(a[2]), "r"(a[3]), "r"(b[0]), "r"(b[1]));
}
__device__ __forceinline__ void ldsm4(uint32_t* r, uint32_t addr){
    asm volatile("ldmatrix.sync.aligned.m8n8.x4.shared.b16 {%0,%1,%2,%3}, [%4];"
        : "=r"(r[0]), "=r"(r[1]), "=r"(r[2]), "=r"(r[3]) : "r"(addr));
}
__device__ __forceinline__ void ldsm4t(uint32_t* r, uint32_t addr){
    asm volatile("ldmatrix.sync.aligned.m8n8.x4.trans.shared.b16 {%0,%1,%2,%3}, [%4];"
        : "=r"(r[0]), "=r"(r[1]), "=r"(r[2]), "=r"(r[3]) : "r"(addr));
}

typedef wmma::fragment<wmma::matrix_a,16,16,16,__nv_bfloat16,wmma::row_major> AFrag;
typedef wmma::fragment<wmma::matrix_b,16,16,16,__nv_bfloat16,wmma::col_major> BFragC;
typedef wmma::fragment<wmma::accumulator,16,16,16,float> CFrag;

// ---------------------------------------------------------------------------
// split kernels (bf16, GEMM inputs)
// ---------------------------------------------------------------------------
__global__ __launch_bounds__(256) void split_x_kernel(
    const float* __restrict__ in, __nv_bfloat16* __restrict__ hi,
    __nv_bfloat16* __restrict__ lo)
{
    int i = blockIdx.x*256 + threadIdx.x;
    float4 v = ((const float4*)in)[i];
    store_split4(hi + 4*(size_t)i, lo + 4*(size_t)i, v);
}
// Slot order: 0=Wq, 1=Wv(->K), 2=Wk(->V), 3=Wo
__global__ __launch_bounds__(256) void split_w_kernel(
    const float* __restrict__ Wq, const float* __restrict__ Wv,
    const float* __restrict__ Wk, const float* __restrict__ Wo,
    __nv_bfloat16* __restrict__ hi, __nv_bfloat16* __restrict__ lo)
{
    int slot = blockIdx.x >> 10;
    const float* src = slot==0 ? Wq : slot==1 ? Wv : slot==2 ? Wk : Wo;
    int i = (blockIdx.x & 1023)*256 + threadIdx.x;
    float4 v = ((const float4*)src)[i];
    size_t o = (size_t)slot*DD + 4*(size_t)i;
    store_split4(hi + o, lo + o, v);
}

// ---------------------------------------------------------------------------
// GEMM mainloop core (bf16 3-mma split), cp.async double-buffered.
// ---------------------------------------------------------------------------
#define GS 40
#define GMAT (128*GS)
#define G_SMEM (2*4*GMAT*2)       // 81920 bytes

__device__ __forceinline__ void gemm_core(
    const __nv_bfloat16* __restrict__ Agh, const __nv_bfloat16* __restrict__ Agl,
    const __nv_bfloat16* __restrict__ Bgh, const __nv_bfloat16* __restrict__ Bgl,
    __nv_bfloat16* sm, uint32_t sbase, int tid, int wm, int wn,
    int m0, int n0, CFrag (&acc)[2][4])
{
#define G_LOAD(k0, bsel) do { \
    uint32_t s0 = sbase + (uint32_t)((bsel)*4*GMAT)*2; \
    _Pragma("unroll") \
    for (int i=0;i<2;i++){ \
        int g = tid + i*256; \
        int r = g>>2, c8 = g&3; \
        uint32_t so = s0 + (uint32_t)(r*GS + c8*8)*2; \
        size_t ga = (size_t)(m0+r)*Dc + (k0) + c8*8; \
        size_t gb = (size_t)(n0+r)*Dc + (k0) + c8*8; \
        cpasync16(so,              Agh + ga); \
        cpasync16(so + 2*GMAT,     Agl + ga); \
        cpasync16(so + 4*GMAT,     Bgh + gb); \
        cpasync16(so + 6*GMAT,     Bgl + gb); \
    } } while(0)

    G_LOAD(0, 0);
    CP_COMMIT();

    for (int ch=0; ch<32; ch++){
        if (ch < 31){ G_LOAD((ch+1)*32, (ch+1)&1); CP_COMMIT(); CP_WAIT1(); }
        else CP_WAIT0();
        __syncthreads();

        const __nv_bfloat16* Ah = sm + (ch&1)*4*GMAT;
        const __nv_bfloat16* Al = Ah + GMAT;
        const __nv_bfloat16* Bh = Ah + 2*GMAT;
        const __nv_bfloat16* Bl = Ah + 3*GMAT;
#pragma unroll
        for (int st=0; st<2; st++){
            AFrag ah[2], al[2];
#pragma unroll
            for (int im=0;im<2;im++){
                wmma::load_matrix_sync(ah[im], Ah + (wm*32+im*16)*GS + st*16, GS);
                wmma::load_matrix_sync(al[im], Al + (wm*32+im*16)*GS + st*16, GS);
            }
#pragma unroll
            for (int in=0;in<4;in++){
                BFragC bh_, bl_;
                wmma::load_matrix_sync(bh_, Bh + (wn*64+in*16)*GS + st*16, GS);
                wmma::load_matrix_sync(bl_, Bl + (wn*64+in*16)*GS + st*16, GS);
#pragma unroll
                for (int im=0;im<2;im++){
                    wmma::mma_sync(acc[im][in], ah[im], bh_, acc[im][in]);
                    wmma::mma_sync(acc[im][in], ah[im], bl_, acc[im][in]);
                    wmma::mma_sync(acc[im][in], al[im], bh_, acc[im][in]);
                }
            }
        }
        __syncthreads();
    }
#undef G_LOAD
}

// ---------------------------------------------------------------------------
// Fused projection GEMM: grid (24, 32). slot = blockIdx.x>>3.
// Epilogue: bias + xPos rotary, writes fp16 flash operands:
//   slot 0 (Q): *sc*log2e/32, fp16 hi/lo -> Qh,Ql
//   slot 1 (K): /sc, single fp16 -> Kh
//   slot 2 (V): bias only, single fp16 -> Vh
// xPos trig uses powf/sincosf to track the fp32 reference numerics.
// ---------------------------------------------------------------------------
#define STS 132

__global__ __launch_bounds__(256) void gemm_proj(
    const __nv_bfloat16* __restrict__ Agh, const __nv_bfloat16* __restrict__ Agl,
    const __nv_bfloat16* __restrict__ Wh,  const __nv_bfloat16* __restrict__ Wl,
    const float* __restrict__ bq, const float* __restrict__ bv,
    const float* __restrict__ bk,
    __half* __restrict__ Qh, __half* __restrict__ Ql,
    __half* __restrict__ Kh, __half* __restrict__ Vh)
{
    extern __shared__ __nv_bfloat16 sm[];
    uint32_t sbase = smem_u32(sm);
    const int tid = threadIdx.x, wid = tid>>5;
    const int wm = wid>>1, wn = wid&1;
    const int slot = blockIdx.x>>3;
    const int m0 = blockIdx.y*128, n0 = (blockIdx.x&7)*128;

    CFrag acc[2][4];
#pragma unroll
    for (int i=0;i<2;i++)
#pragma unroll
      for (int j=0;j<4;j++) wmma::fill_fragment(acc[i][j], 0.0f);

    gemm_core(Agh, Agl, Wh + (size_t)slot*DD, Wl + (size_t)slot*DD,
              sm, sbase, tid, wm, wn, m0, n0, acc);

    float* stf = (float*)sm;
#pragma unroll
    for (int im=0;im<2;im++)
#pragma unroll
      for (int in=0;in<4;in++)
        wmma::store_matrix_sync(&stf[(wm*32+im*16)*STS + wn*64+in*16],
                                acc[im][in], STS, wmma::mem_row_major);
    __syncthreads();

    const float* bias = slot==0 ? bq : slot==1 ? bv : bk;
#pragma unroll
    for (int i=0;i<32;i++){
        int idx = tid + i*256;
        int r = idx>>6, cp = idx&63;
        int cc = n0 + 2*cp;
        float a  = stf[r*STS + 2*cp]     + bias[cc];
        float b2 = stf[r*STS + 2*cp + 1] + bias[cc+1];
        size_t base = (size_t)(m0 + r)*Dc + cc;
        if (slot == 2){
            *(uint32_t*)(Vh + base) = pack2h_single(a, b2);
        } else {
            int m = m0 + r, l = m & (Lc-1), j = cc & 63;
            float jf = (float)j;
            float inv_freq = powf(10000.0f, -jf * (1.0f/64.0f));
            float fr = (float)l * inv_freq;
            float sn, cs; sincosf(fr, &sn, &cs);
            float sv = (jf + 25.6f) * (1.0f/89.6f);
            float pw = ((float)l - 1024.0f) * (1.0f/512.0f);
            float sc = powf(sv, pw);
            if (slot == 0){
                float s = sc * (0.03125f * 1.4426950408889634f);
                float o0 = (a*cs - b2*sn) * s;
                float o1 = (b2*cs + a*sn) * s;
                uint32_t lo, hi = pack2h(o0, o1, lo);
                *(uint32_t*)(Qh + base) = hi;
                *(uint32_t*)(Ql + base) = lo;
            } else {
                float s = 1.0f/sc;
                float o0 = (a*cs - b2*sn) * s;
                float o1 = (b2*cs + a*sn) * s;
                *(uint32_t*)(Kh + base) = pack2h_single(o0, o1);
            }
        }
    }
}

// ---------------------------------------------------------------------------
// Output GEMM: out = T @ Wo^T + bo (bf16 3-mma, f32 out, bias fused)
// ---------------------------------------------------------------------------
__global__ __launch_bounds__(256) void gemm_out(
    const __nv_bfloat16* __restrict__ Agh, const __nv_bfloat16* __restrict__ Agl,
    const __nv_bfloat16* __restrict__ Wh,  const __nv_bfloat16* __restrict__ Wl,
    const float* __restrict__ bo, float* __restrict__ out)
{
    extern __shared__ __nv_bfloat16 sm[];
    uint32_t sbase = smem_u32(sm);
    const int tid = threadIdx.x, wid = tid>>5;
    const int wm = wid>>1, wn = wid&1;
    const int m0 = blockIdx.y*128, n0 = blockIdx.x*128;

    CFrag acc[2][4];
#pragma unroll
    for (int i=0;i<2;i++)
#pragma unroll
      for (int j=0;j<4;j++) wmma::fill_fragment(acc[i][j], 0.0f);

    gemm_core(Agh, Agl, Wh, Wl, sm, sbase, tid, wm, wn, m0, n0, acc);

    float* stf = (float*)sm;
#pragma unroll
    for (int im=0;im<2;im++)
#pragma unroll
      for (int in=0;in<4;in++)
        wmma::store_matrix_sync(&stf[(wm*32+im*16)*STS + wn*64+in*16],
                                acc[im][in], STS, wmma::mem_row_major);
    __syncthreads();

#pragma unroll
    for (int i=0;i<16;i++){
        int idx = tid + i*256;
        int r = idx>>5, c4 = (idx&31)<<2;
        float4 v;
        v.x = stf[r*STS + c4]     + bo[n0+c4];
        v.y = stf[r*STS + c4 + 1] + bo[n0+c4+1];
        v.z = stf[r*STS + c4 + 2] + bo[n0+c4+2];
        v.w = stf[r*STS + c4 + 3] + bo[n0+c4+3];
        *(float4*)&out[(size_t)(m0+r)*Dc + n0 + c4] = v;
    }
}

// ---------------------------------------------------------------------------
// Single-pass FA2, fp16 operands:
//   S = (Qh+Ql) K  -> 2 mma/n8   O += (Ph+Pl) V -> 2 mma/n8
// 3-stage cp.async K/V pipeline, ONE barrier per tile, exp2 softmax
// (Q carries log2e/32*sc). CTA: 128 q-rows x (b,h); 8 warps; 64-key tiles.
// ---------------------------------------------------------------------------
#define FSD 72
#define FSLICE (64*FSD)           // half elems per 64x64 slice
#define FBUF (2*FSLICE)           // Kh, Vh per stage
#define NSTAGE 3
#define FL_SMEM (NSTAGE*FBUF*2)   // 55296 bytes

__global__ __launch_bounds__(256) void flash_kernel(
    const __half* __restrict__ Qhg, const __half* __restrict__ Qlg,
    const __half* __restrict__ Khg, const __half* __restrict__ Vhg,
    __nv_bfloat16* __restrict__ Th, __nv_bfloat16* __restrict__ Tl)
{
    extern __shared__ __half smf[];
    uint32_t sbase = smem_u32(smf);

    const int tid = threadIdx.x;
    const int w = tid>>5, L = tid&31;
    const int lr = L&7;
    const int qt = blockIdx.x, bh = blockIdx.y;
    const int b = bh>>4, h = bh&15;
    const size_t qrow0 = (size_t)b*Lc + qt*128;
    const size_t krow0 = (size_t)b*Lc;

    // ---- stage Q (128x64, hi+lo fp16) via cp.async ----
#pragma unroll
    for (int i=0;i<8;i++){
        int sl = i>>2;
        int gg = tid + (i&3)*256;
        int r = gg>>3, c8 = gg&7;
        const __half* src = sl ? Qlg : Qhg;
        uint32_t so = sbase + (uint32_t)(sl*128*FSD + r*FSD + c8*8)*2;
        cpasync16(so, src + (qrow0 + r)*Dc + h*64 + c8*8);
    }
    CP_COMMIT(); CP_WAIT0();
    __syncthreads();

    // ---- Q fragments to registers ----
    uint32_t qh[4][4], ql[4][4];
    {
        int g = L>>3;
        int qrow = w*16 + (g&1)*8 + lr;
        int qcol = (g>>1)*8;
#pragma unroll
        for (int kk=0;kk<4;kk++){
            ldsm4(qh[kk], smem_u32(smf + qrow*FSD + kk*16 + qcol));
            ldsm4(ql[kk], smem_u32(smf + 128*FSD + qrow*FSD + kk*16 + qcol));
        }
    }
    __syncthreads();

    float Oa[8][4];
#pragma unroll
    for (int n=0;n<8;n++){ Oa[n][0]=0.f; Oa[n][1]=0.f; Oa[n][2]=0.f; Oa[n][3]=0.f; }
    float m0r = -1e30f, m1r = -1e30f, l0r = 0.f, l1r = 0.f;

    const uint32_t krow_base = ((L>>4)<<3) + lr;
    const uint32_t kcol_base = ((L>>3)&1)<<3;
    const uint32_t vrow_base = (((L>>3)&1)<<3) + lr;
    const uint32_t vcol_base = (L>>4)<<3;

    // 2 slices per tile: Kh(0), Vh(1); 1024 16B chunks -> 4 per thread
#define KV_LOAD(kt_, bsel) do { \
    _Pragma("unroll") \
    for (int i=0;i<4;i++){ \
        int sl = i>>1; \
        int gg = tid + (i&1)*256; \
        int r = gg>>3, c8 = gg&7; \
        const __half* src = sl ? Vhg : Khg; \
        uint32_t so = sbase + (uint32_t)((bsel)*FBUF + sl*FSLICE + r*FSD + c8*8)*2; \
        cpasync16(so, src + (krow0 + (kt_)*64 + r)*Dc + h*64 + c8*8); \
    } } while(0)

    KV_LOAD(0, 0); CP_COMMIT();
    KV_LOAD(1, 1); CP_COMMIT();

    const int NT = Lc/64;
    for (int kt=0; kt<NT; kt++){
        if (kt+2 < NT) CP_WAIT1(); else CP_WAIT0();
        __syncthreads();
        if (kt+2 < NT){ KV_LOAD(kt+2, (kt+2)%NSTAGE); CP_COMMIT(); }

        const __half* Khs = smf + (kt%NSTAGE)*FBUF;
        const __half* Vhs = Khs + FSLICE;

        // ---- S = Q K^T (2 mma per n8 block) ----
        float S[8][4];
#pragma unroll
        for (int j=0;j<8;j++){ S[j][0]=0.f; S[j][1]=0.f; S[j][2]=0.f; S[j][3]=0.f; }
#pragma unroll
        for (int kk=0;kk<4;kk++){
#pragma unroll
            for (int jp=0;jp<4;jp++){
                uint32_t kh4[4];
                uint32_t a = (uint32_t)((jp*16 + krow_base)*FSD + kk*16 + kcol_base);
                ldsm4(kh4, smem_u32(Khs + a));
                mma16816h(S[2*jp],   qh[kk], kh4);
                mma16816h(S[2*jp],   ql[kk], kh4);
                mma16816h(S[2*jp+1], qh[kk], kh4+2);
                mma16816h(S[2*jp+1], ql[kk], kh4+2);
            }
        }

        // ---- online softmax (exp2 domain) ----
        float lm0 = -1e30f, lm1 = -1e30f;
#pragma unroll
        for (int j=0;j<8;j++){
            lm0 = fmaxf(lm0, fmaxf(S[j][0], S[j][1]));
            lm1 = fmaxf(lm1, fmaxf(S[j][2], S[j][3]));
        }
        lm0 = fmaxf(lm0, __shfl_xor_sync(0xffffffffu, lm0, 1));
        lm0 = fmaxf(lm0, __shfl_xor_sync(0xffffffffu, lm0, 2));
        lm1 = fmaxf(lm1, __shfl_xor_sync(0xffffffffu, lm1, 1));
        lm1 = fmaxf(lm1, __shfl_xor_sync(0xffffffffu, lm1, 2));
        float mn0 = fmaxf(m0r, lm0), mn1 = fmaxf(m1r, lm1);
        float al0 = fexp2(m0r - mn0), al1 = fexp2(m1r - mn1);
        m0r = mn0; m1r = mn1;
        l0r *= al0; l1r *= al1;
#pragma unroll
        for (int n=0;n<8;n++){
            Oa[n][0] *= al0; Oa[n][1] *= al0;
            Oa[n][2] *= al1; Oa[n][3] *= al1;
        }

        float s0 = 0.f, s1 = 0.f;
#pragma unroll
        for (int j=0;j<8;j++){
            S[j][0] = fexp2(S[j][0] - mn0);
            S[j][1] = fexp2(S[j][1] - mn0);
            S[j][2] = fexp2(S[j][2] - mn1);
            S[j][3] = fexp2(S[j][3] - mn1);
            s0 += S[j][0] + S[j][1];
            s1 += S[j][2] + S[j][3];
        }
        s0 += __shfl_xor_sync(0xffffffffu, s0, 1);
        s0 += __shfl_xor_sync(0xffffffffu, s0, 2);
        s1 += __shfl_xor_sync(0xffffffffu, s1, 1);
        s1 += __shfl_xor_sync(0xffffffffu, s1, 2);
        l0r += s0; l1r += s1;

        // ---- P fp16 hi/lo (accumulator layout == A-operand layout) ----
        uint32_t ph[4][4], pl[4][4];
#pragma unroll
        for (int t=0;t<4;t++){
            ph[t][0] = pack2h(S[2*t][0],   S[2*t][1],   pl[t][0]);
            ph[t][1] = pack2h(S[2*t][2],   S[2*t][3],   pl[t][1]);
            ph[t][2] = pack2h(S[2*t+1][0], S[2*t+1][1], pl[t][2]);
            ph[t][3] = pack2h(S[2*t+1][2], S[2*t+1][3], pl[t][3]);
        }

        // ---- O += P V (2 mma per n8 block) ----
#pragma unroll
        for (int t=0;t<4;t++){
#pragma unroll
            for (int np=0;np<4;np++){
                uint32_t vh4[4];
                uint32_t a = (uint32_t)((t*16 + vrow_base)*FSD + np*16 + vcol_base);
                ldsm4t(vh4, smem_u32(Vhs + a));
                mma16816h(Oa[2*np],   ph[t], vh4);
                mma16816h(Oa[2*np],   pl[t], vh4);
                mma16816h(Oa[2*np+1], ph[t], vh4+2);
                mma16816h(Oa[2*np+1], pl[t], vh4+2);
            }
        }
    }

    // ---- normalize + split-store O (bf16 hi/lo for output GEMM) ----
    float inv0 = 1.0f / l0r, inv1 = 1.0f / l1r;
    size_t row0 = qrow0 + w*16 + (L>>2);
    size_t row1 = row0 + 8;
    int colb = h*64 + 2*(L&3);
#pragma unroll
    for (int n=0;n<8;n++){
        uint32_t lo, hi;
        hi = pack2(Oa[n][0]*inv0, Oa[n][1]*inv0, lo);
        *(uint32_t*)(Th + row0*Dc + colb + n*8) = hi;
        *(uint32_t*)(Tl + row0*Dc + colb + n*8) = lo;
        hi = pack2(Oa[n][2]*inv1, Oa[n][3]*inv1, lo);
        *(uint32_t*)(Th + row1*Dc + colb + n*8) = hi;
        *(uint32_t*)(Tl + row1*Dc + colb + n*8) = lo;
    }
}

// ---------------------------------------------------------------------------
extern "C" void kernel_launch(void* const* d_in, const int* in_sizes, int n_in,
                              void* d_out, int out_size)
{
    const float* x  = (const float*)d_in[0];
    const float* Wq = (const float*)d_in[1];
    const float* bq = (const float*)d_in[2];
    const float* Wk = (const float*)d_in[3];
    const float* bk = (const float*)d_in[4];
    const float* Wv = (const float*)d_in[5];
    const float* bv = (const float*)d_in[6];
    const float* Wo = (const float*)d_in[7];
    const float* bo = (const float*)d_in[8];
    float* out = (float*)d_out;

    __nv_bfloat16 *xh, *xl, *Wh, *Wl, *Tph, *Tpl;
    __half *Qh, *Ql, *Kh, *Vh;
    cudaGetSymbolAddress((void**)&xh, g_xh);  cudaGetSymbolAddress((void**)&xl, g_xl);
    cudaGetSymbolAddress((void**)&Wh, g_Wh);  cudaGetSymbolAddress((void**)&Wl, g_Wl);
    cudaGetSymbolAddress((void**)&Qh, g_Qh);  cudaGetSymbolAddress((void**)&Ql, g_Ql);
    cudaGetSymbolAddress((void**)&Kh, g_Kh);
    cudaGetSymbolAddress((void**)&Vh, g_Vh);
    cudaGetSymbolAddress((void**)&Tph, g_Th); cudaGetSymbolAddress((void**)&Tpl, g_Tl);

    cudaFuncSetAttribute(gemm_proj, cudaFuncAttributeMaxDynamicSharedMemorySize, G_SMEM);
    cudaFuncSetAttribute(gemm_out,  cudaFuncAttributeMaxDynamicSharedMemorySize, G_SMEM);
    cudaFuncSetAttribute(flash_kernel, cudaFuncAttributeMaxDynamicSharedMemorySize, FL_SMEM);

    // ---- pre-split x and weights (bf16, 2 launches) ----
    split_x_kernel<<<(NR*Dc/4)/256, 256>>>(x, xh, xl);
    split_w_kernel<<<4*(DD/4)/256, 256>>>(Wq, Wv, Wk, Wo, Wh, Wl);

    // ---- merged projections + fused bias/rope/fp16 epilogue ----
    gemm_proj<<<dim3(24, NR/128), 256, G_SMEM>>>(xh, xl, Wh, Wl,
                                                 bq, bv, bk,
                                                 Qh, Ql, Kh, Vh);

    // ---- single-pass flash attention (fp16 operands) ----
    flash_kernel<<<dim3(Lc/128, Bc*16), 256, FL_SMEM>>>(Qh, Ql, Kh, Vh,
                                                        Tph, Tpl);

    // ---- output projection + fused bias ----
    gemm_out<<<dim3(Dc/128, NR/128), 256, G_SMEM>>>(Tph, Tpl, Wh + 3*(size_t)DD,
                                                    Wl + 3*(size_t)DD, bo, out);
}

// round 14
// speedup vs baseline: 5.1173x; 1.1126x over previous
#include <cuda_runtime.h>
#include <cuda_bf16.h>
#include <cuda_fp16.h>
#include <mma.h>
#include <math.h>
#include <stdint.h>

using namespace nvcuda;

#define Bc 2
#define Lc 2048
#define Dc 1024
#define NR (Bc*Lc)
#define DD (Dc*Dc)

// pre-split bf16 operands (GEMM inputs)
__device__ __nv_bfloat16 g_xh[NR*Dc], g_xl[NR*Dc];
__device__ __nv_bfloat16 g_Wh[4*DD],  g_Wl[4*DD];
// fp16 flash operands (Q hi/lo, K hi/lo, V single)
__device__ __half g_Qh[NR*Dc], g_Ql[NR*Dc];
__device__ __half g_Kh[NR*Dc], g_Kl[NR*Dc];
__device__ __half g_Vh[NR*Dc];
// flash output, split bf16 for output GEMM
__device__ __nv_bfloat16 g_Th[NR*Dc], g_Tl[NR*Dc];

// ---------------------------------------------------------------------------
// helpers
// ---------------------------------------------------------------------------
__device__ __forceinline__ uint32_t smem_u32(const void* p){
    uint32_t a;
    asm("{ .reg .u64 t; cvta.to.shared.u64 t, %1; cvt.u32.u64 %0, t; }"
        : "=r"(a) : "l"(p));
    return a;
}
__device__ __forceinline__ float fexp2(float x){
    float y; asm("ex2.approx.f32 %0, %1;" : "=f"(y) : "f"(x)); return y;
}
// bf16 hi/lo split pack
__device__ __forceinline__ uint32_t pack2(float a, float b, uint32_t& lo){
    __nv_bfloat16 ha = __float2bfloat16(a), hb = __float2bfloat16(b);
    __nv_bfloat16 la = __float2bfloat16(a - __bfloat162float(ha));
    __nv_bfloat16 lb = __float2bfloat16(b - __bfloat162float(hb));
    lo = (uint32_t)__bfloat16_as_ushort(la) | ((uint32_t)__bfloat16_as_ushort(lb)<<16);
    return (uint32_t)__bfloat16_as_ushort(ha) | ((uint32_t)__bfloat16_as_ushort(hb)<<16);
}
__device__ __forceinline__ void store_split4(void* ph, void* pl, float4 v){
    uint2 H, L;
    H.x = pack2(v.x, v.y, L.x);
    H.y = pack2(v.z, v.w, L.y);
    *(uint2*)ph = H;
    *(uint2*)pl = L;
}
// fp16 hi/lo split pack
__device__ __forceinline__ uint32_t pack2h(float a, float b, uint32_t& lo){
    __half ha = __float2half(a), hb = __float2half(b);
    __half la = __float2half(a - __half2float(ha));
    __half lb = __float2half(b - __half2float(hb));
    lo = (uint32_t)__half_as_ushort(la) | ((uint32_t)__half_as_ushort(lb)<<16);
    return (uint32_t)__half_as_ushort(ha) | ((uint32_t)__half_as_ushort(hb)<<16);
}
__device__ __forceinline__ uint32_t pack2h_single(float a, float b){
    __half ha = __float2half(a), hb = __float2half(b);
    return (uint32_t)__half_as_ushort(ha) | ((uint32_t)__half_as_ushort(hb)<<16);
}
__device__ __forceinline__ void cpasync16(uint32_t saddr, const void* g){
    asm volatile("cp.async.ca.shared.global [%0], [%1], 16;" :: "r"(saddr), "l"(g));
}
#define CP_COMMIT() asm volatile("cp.async.commit_group;" ::: "memory")
#define CP_WAIT1()  asm volatile("cp.async.wait_group 1;" ::: "memory")
#define CP_WAIT0()  asm volatile("cp.async.wait_group 0;" ::: "memory")

__device__ __forceinline__ void mma16816h(float* d, const uint32_t* a, const uint32_t* b){
    asm volatile(
        "mma.sync.aligned.m16n8k16.row.col.f32.f16.f16.f32 "
        "{%0,%1,%2,%3}, {%4,%5,%6,%7}, {%8,%9}, {%0,%1,%2,%3};"
        : "+f"(d[0]), "+f"(d[1]), "+f"(d[2]), "+f"(d[3])
        : "r"(a[0]), "r"(a[1]), "r"(a[2]), "r"(a[3]), "r"(b[0]), "r"(b[1]));
}
__device__ __forceinline__ void ldsm4(uint32_t* r, uint32_t addr){
    asm volatile("ldmatrix.sync.aligned.m8n8.x4.shared.b16 {%0,%1,%2,%3}, [%4];"
        : "=r"(r[0]), "=r"(r[1]), "=r"(r[2]), "=r"(r[3]) : "r"(addr));
}
__device__ __forceinline__ void ldsm4t(uint32_t* r, uint32_t addr){
    asm volatile("ldmatrix.sync.aligned.m8n8.x4.trans.shared.b16 {%0,%1,%2,%3}, [%4];"
        : "=r"(r[0]), "=r"(r[1]), "=r"(r[2]), "=r"(r[3]) : "r"(addr));
}

typedef wmma::fragment<wmma::matrix_a,16,16,16,__nv_bfloat16,wmma::row_major> AFrag;
typedef wmma::fragment<wmma::matrix_b,16,16,16,__nv_bfloat16,wmma::col_major> BFragC;
typedef wmma::fragment<wmma::accumulator,16,16,16,float> CFrag;

// ---------------------------------------------------------------------------
// split kernels (bf16, GEMM inputs)
// ---------------------------------------------------------------------------
__global__ __launch_bounds__(256) void split_x_kernel(
    const float* __restrict__ in, __nv_bfloat16* __restrict__ hi,
    __nv_bfloat16* __restrict__ lo)
{
    int i = blockIdx.x*256 + threadIdx.x;
    float4 v = ((const float4*)in)[i];
    store_split4(hi + 4*(size_t)i, lo + 4*(size_t)i, v);
}
// Slot order: 0=Wq, 1=Wv(->K), 2=Wk(->V), 3=Wo
__global__ __launch_bounds__(256) void split_w_kernel(
    const float* __restrict__ Wq, const float* __restrict__ Wv,
    const float* __restrict__ Wk, const float* __restrict__ Wo,
    __nv_bfloat16* __restrict__ hi, __nv_bfloat16* __restrict__ lo)
{
    int slot = blockIdx.x >> 10;
    const float* src = slot==0 ? Wq : slot==1 ? Wv : slot==2 ? Wk : Wo;
    int i = (blockIdx.x & 1023)*256 + threadIdx.x;
    float4 v = ((const float4*)src)[i];
    size_t o = (size_t)slot*DD + 4*(size_t)i;
    store_split4(hi + o, lo + o, v);
}

// ---------------------------------------------------------------------------
// GEMM mainloop core (bf16 3-mma split), cp.async double-buffered.
// ---------------------------------------------------------------------------
#define GS 40
#define GMAT (128*GS)
#define G_SMEM (2*4*GMAT*2)       // 81920 bytes

__device__ __forceinline__ void gemm_core(
    const __nv_bfloat16* __restrict__ Agh, const __nv_bfloat16* __restrict__ Agl,
    const __nv_bfloat16* __restrict__ Bgh, const __nv_bfloat16* __restrict__ Bgl,
    __nv_bfloat16* sm, uint32_t sbase, int tid, int wm, int wn,
    int m0, int n0, CFrag (&acc)[2][4])
{
#define G_LOAD(k0, bsel) do { \
    uint32_t s0 = sbase + (uint32_t)((bsel)*4*GMAT)*2; \
    _Pragma("unroll") \
    for (int i=0;i<2;i++){ \
        int g = tid + i*256; \
        int r = g>>2, c8 = g&3; \
        uint32_t so = s0 + (uint32_t)(r*GS + c8*8)*2; \
        size_t ga = (size_t)(m0+r)*Dc + (k0) + c8*8; \
        size_t gb = (size_t)(n0+r)*Dc + (k0) + c8*8; \
        cpasync16(so,              Agh + ga); \
        cpasync16(so + 2*GMAT,     Agl + ga); \
        cpasync16(so + 4*GMAT,     Bgh + gb); \
        cpasync16(so + 6*GMAT,     Bgl + gb); \
    } } while(0)

    G_LOAD(0, 0);
    CP_COMMIT();

    for (int ch=0; ch<32; ch++){
        if (ch < 31){ G_LOAD((ch+1)*32, (ch+1)&1); CP_COMMIT(); CP_WAIT1(); }
        else CP_WAIT0();
        __syncthreads();

        const __nv_bfloat16* Ah = sm + (ch&1)*4*GMAT;
        const __nv_bfloat16* Al = Ah + GMAT;
        const __nv_bfloat16* Bh = Ah + 2*GMAT;
        const __nv_bfloat16* Bl = Ah + 3*GMAT;
#pragma unroll
        for (int st=0; st<2; st++){
            AFrag ah[2], al[2];
#pragma unroll
            for (int im=0;im<2;im++){
                wmma::load_matrix_sync(ah[im], Ah + (wm*32+im*16)*GS + st*16, GS);
                wmma::load_matrix_sync(al[im], Al + (wm*32+im*16)*GS + st*16, GS);
            }
#pragma unroll
            for (int in=0;in<4;in++){
                BFragC bh_, bl_;
                wmma::load_matrix_sync(bh_, Bh + (wn*64+in*16)*GS + st*16, GS);
                wmma::load_matrix_sync(bl_, Bl + (wn*64+in*16)*GS + st*16, GS);
#pragma unroll
                for (int im=0;im<2;im++){
                    wmma::mma_sync(acc[im][in], ah[im], bh_, acc[im][in]);
                    wmma::mma_sync(acc[im][in], ah[im], bl_, acc[im][in]);
                    wmma::mma_sync(acc[im][in], al[im], bh_, acc[im][in]);
                }
            }
        }
        __syncthreads();
    }
#undef G_LOAD
}

// ---------------------------------------------------------------------------
// Fused projection GEMM: grid (24, 32). slot = blockIdx.x>>3.
// Epilogue: bias + xPos rotary, writes fp16 flash operands:
//   slot 0 (Q): *sc*log2e/32, fp16 hi/lo -> Qh,Ql
//   slot 1 (K): /sc, fp16 hi/lo -> Kh,Kl
//   slot 2 (V): bias only, single fp16 -> Vh
// ---------------------------------------------------------------------------
#define STS 132

__global__ __launch_bounds__(256, 2) void gemm_proj(
    const __nv_bfloat16* __restrict__ Agh, const __nv_bfloat16* __restrict__ Agl,
    const __nv_bfloat16* __restrict__ Wh,  const __nv_bfloat16* __restrict__ Wl,
    const float* __restrict__ bq, const float* __restrict__ bv,
    const float* __restrict__ bk,
    __half* __restrict__ Qh, __half* __restrict__ Ql,
    __half* __restrict__ Kh, __half* __restrict__ Kl,
    __half* __restrict__ Vh)
{
    extern __shared__ __nv_bfloat16 sm[];
    uint32_t sbase = smem_u32(sm);
    const int tid = threadIdx.x, wid = tid>>5;
    const int wm = wid>>1, wn = wid&1;
    const int slot = blockIdx.x>>3;
    const int m0 = blockIdx.y*128, n0 = (blockIdx.x&7)*128;

    CFrag acc[2][4];
#pragma unroll
    for (int i=0;i<2;i++)
#pragma unroll
      for (int j=0;j<4;j++) wmma::fill_fragment(acc[i][j], 0.0f);

    gemm_core(Agh, Agl, Wh + (size_t)slot*DD, Wl + (size_t)slot*DD,
              sm, sbase, tid, wm, wn, m0, n0, acc);

    float* stf = (float*)sm;
#pragma unroll
    for (int im=0;im<2;im++)
#pragma unroll
      for (int in=0;in<4;in++)
        wmma::store_matrix_sync(&stf[(wm*32+im*16)*STS + wn*64+in*16],
                                acc[im][in], STS, wmma::mem_row_major);
    __syncthreads();

    const float* bias = slot==0 ? bq : slot==1 ? bv : bk;
#pragma unroll
    for (int i=0;i<32;i++){
        int idx = tid + i*256;
        int r = idx>>6, cp = idx&63;
        int cc = n0 + 2*cp;
        float a  = stf[r*STS + 2*cp]     + bias[cc];
        float b2 = stf[r*STS + 2*cp + 1] + bias[cc+1];
        size_t base = (size_t)(m0 + r)*Dc + cc;
        if (slot == 2){
            *(uint32_t*)(Vh + base) = pack2h_single(a, b2);
        } else {
            int m = m0 + r, l = m & (Lc-1), j = cc & 63;
            float jf = (float)j;
            float inv_freq = powf(10000.0f, -jf * (1.0f/64.0f));
            float fr = (float)l * inv_freq;
            float sn, cs; sincosf(fr, &sn, &cs);
            float sv = (jf + 25.6f) * (1.0f/89.6f);
            float pw = ((float)l - 1024.0f) * (1.0f/512.0f);
            float sc = powf(sv, pw);
            float s = (slot==0) ? sc * (0.03125f * 1.4426950408889634f)
                                : 1.0f/sc;
            float o0 = (a*cs - b2*sn) * s;
            float o1 = (b2*cs + a*sn) * s;
            uint32_t lo, hi = pack2h(o0, o1, lo);
            __half* Dh = (slot==0) ? Qh : Kh;
            __half* Dl = (slot==0) ? Ql : Kl;
            *(uint32_t*)(Dh + base) = hi;
            *(uint32_t*)(Dl + base) = lo;
        }
    }
}

// ---------------------------------------------------------------------------
// Output GEMM: out = T @ Wo^T + bo (bf16 3-mma, f32 out, bias fused)
// ---------------------------------------------------------------------------
__global__ __launch_bounds__(256, 2) void gemm_out(
    const __nv_bfloat16* __restrict__ Agh, const __nv_bfloat16* __restrict__ Agl,
    const __nv_bfloat16* __restrict__ Wh,  const __nv_bfloat16* __restrict__ Wl,
    const float* __restrict__ bo, float* __restrict__ out)
{
    extern __shared__ __nv_bfloat16 sm[];
    uint32_t sbase = smem_u32(sm);
    const int tid = threadIdx.x, wid = tid>>5;
    const int wm = wid>>1, wn = wid&1;
    const int m0 = blockIdx.y*128, n0 = blockIdx.x*128;

    CFrag acc[2][4];
#pragma unroll
    for (int i=0;i<2;i++)
#pragma unroll
      for (int j=0;j<4;j++) wmma::fill_fragment(acc[i][j], 0.0f);

    gemm_core(Agh, Agl, Wh, Wl, sm, sbase, tid, wm, wn, m0, n0, acc);

    float* stf = (float*)sm;
#pragma unroll
    for (int im=0;im<2;im++)
#pragma unroll
      for (int in=0;in<4;in++)
        wmma::store_matrix_sync(&stf[(wm*32+im*16)*STS + wn*64+in*16],
                                acc[im][in], STS, wmma::mem_row_major);
    __syncthreads();

#pragma unroll
    for (int i=0;i<16;i++){
        int idx = tid + i*256;
        int r = idx>>5, c4 = (idx&31)<<2;
        float4 v;
        v.x = stf[r*STS + c4]     + bo[n0+c4];
        v.y = stf[r*STS + c4 + 1] + bo[n0+c4+1];
        v.z = stf[r*STS + c4 + 2] + bo[n0+c4+2];
        v.w = stf[r*STS + c4 + 3] + bo[n0+c4+3];
        *(float4*)&out[(size_t)(m0+r)*Dc + n0 + c4] = v;
    }
}

// ---------------------------------------------------------------------------
// Single-pass FA2, fp16 operands:
//   S = (Qh+Ql)·Kh + Qh·Kl  (3 mma/n8, near-exact)
//   O += Ps·Vs              (1 mma/n8, P single fp16)
// 3-stage cp.async pipeline (Kh,Kl,Vh), exp2 softmax, 2 CTAs/SM.
// CTA: 128 q-rows x (b,h); 8 warps; 64-key tiles.
// ---------------------------------------------------------------------------
#define FSD 72
#define FSLICE (64*FSD)           // half elems per 64x64 slice
#define FBUF (3*FSLICE)           // Kh, Kl, Vh per stage
#define NSTAGE 3
#define FL_SMEM (NSTAGE*FBUF*2)   // 82944 bytes

__global__ __launch_bounds__(256, 2) void flash_kernel(
    const __half* __restrict__ Qhg, const __half* __restrict__ Qlg,
    const __half* __restrict__ Khg, const __half* __restrict__ Klg,
    const __half* __restrict__ Vhg,
    __nv_bfloat16* __restrict__ Th, __nv_bfloat16* __restrict__ Tl)
{
    extern __shared__ __half smf[];
    uint32_t sbase = smem_u32(smf);

    const int tid = threadIdx.x;
    const int w = tid>>5, L = tid&31;
    const int lr = L&7;
    const int qt = blockIdx.x, bh = blockIdx.y;
    const int b = bh>>4, h = bh&15;
    const size_t qrow0 = (size_t)b*Lc + qt*128;
    const size_t krow0 = (size_t)b*Lc;

    // ---- stage Q (128x64, hi+lo fp16) via cp.async ----
#pragma unroll
    for (int i=0;i<8;i++){
        int sl = i>>2;
        int gg = tid + (i&3)*256;
        int r = gg>>3, c8 = gg&7;
        const __half* src = sl ? Qlg : Qhg;
        uint32_t so = sbase + (uint32_t)(sl*128*FSD + r*FSD + c8*8)*2;
        cpasync16(so, src + (qrow0 + r)*Dc + h*64 + c8*8);
    }
    CP_COMMIT(); CP_WAIT0();
    __syncthreads();

    // ---- Q fragments to registers ----
    uint32_t qh[4][4], ql[4][4];
    {
        int g = L>>3;
        int qrow = w*16 + (g&1)*8 + lr;
        int qcol = (g>>1)*8;
#pragma unroll
        for (int kk=0;kk<4;kk++){
            ldsm4(qh[kk], smem_u32(smf + qrow*FSD + kk*16 + qcol));
            ldsm4(ql[kk], smem_u32(smf + 128*FSD + qrow*FSD + kk*16 + qcol));
        }
    }
    __syncthreads();

    float Oa[8][4];
#pragma unroll
    for (int n=0;n<8;n++){ Oa[n][0]=0.f; Oa[n][1]=0.f; Oa[n][2]=0.f; Oa[n][3]=0.f; }
    float m0r = -1e30f, m1r = -1e30f, l0r = 0.f, l1r = 0.f;

    const uint32_t krow_base = ((L>>4)<<3) + lr;
    const uint32_t kcol_base = ((L>>3)&1)<<3;
    const uint32_t vrow_base = (((L>>3)&1)<<3) + lr;
    const uint32_t vcol_base = (L>>4)<<3;

    // 3 slices per tile: Kh(0), Kl(1), Vh(2); 512 chunks each -> 6 per thread
#define KV_LOAD(kt_, bsel) do { \
    _Pragma("unroll") \
    for (int i=0;i<6;i++){ \
        int sl = i>>1; \
        int gg = tid + (i&1)*256; \
        int r = gg>>3, c8 = gg&7; \
        const __half* src = (sl==0)?Khg:(sl==1)?Klg:Vhg; \
        uint32_t so = sbase + (uint32_t)((bsel)*FBUF + sl*FSLICE + r*FSD + c8*8)*2; \
        cpasync16(so, src + (krow0 + (kt_)*64 + r)*Dc + h*64 + c8*8); \
    } } while(0)

    KV_LOAD(0, 0); CP_COMMIT();
    KV_LOAD(1, 1); CP_COMMIT();

    const int NT = Lc/64;
    for (int kt=0; kt<NT; kt++){
        if (kt+2 < NT) CP_WAIT1(); else CP_WAIT0();
        __syncthreads();
        if (kt+2 < NT){ KV_LOAD(kt+2, (kt+2)%NSTAGE); CP_COMMIT(); }

        const __half* Khs = smf + (kt%NSTAGE)*FBUF;
        const __half* Kls = Khs + FSLICE;
        const __half* Vhs = Khs + 2*FSLICE;

        // ---- S = (Qh+Ql)Kh + Qh·Kl (3 mma per n8 block) ----
        float S[8][4];
#pragma unroll
        for (int j=0;j<8;j++){ S[j][0]=0.f; S[j][1]=0.f; S[j][2]=0.f; S[j][3]=0.f; }
#pragma unroll
        for (int kk=0;kk<4;kk++){
#pragma unroll
            for (int jp=0;jp<4;jp++){
                uint32_t kh4[4], kl4[4];
                uint32_t a = (uint32_t)((jp*16 + krow_base)*FSD + kk*16 + kcol_base);
                ldsm4(kh4, smem_u32(Khs + a));
                ldsm4(kl4, smem_u32(Kls + a));
                mma16816h(S[2*jp],   qh[kk], kh4);
                mma16816h(S[2*jp],   ql[kk], kh4);
                mma16816h(S[2*jp],   qh[kk], kl4);
                mma16816h(S[2*jp+1], qh[kk], kh4+2);
                mma16816h(S[2*jp+1], ql[kk], kh4+2);
                mma16816h(S[2*jp+1], qh[kk], kl4+2);
            }
        }

        // ---- online softmax (exp2 domain) ----
        float lm0 = -1e30f, lm1 = -1e30f;
#pragma unroll
        for (int j=0;j<8;j++){
            lm0 = fmaxf(lm0, fmaxf(S[j][0], S[j][1]));
            lm1 = fmaxf(lm1, fmaxf(S[j][2], S[j][3]));
        }
        lm0 = fmaxf(lm0, __shfl_xor_sync(0xffffffffu, lm0, 1));
        lm0 = fmaxf(lm0, __shfl_xor_sync(0xffffffffu, lm0, 2));
        lm1 = fmaxf(lm1, __shfl_xor_sync(0xffffffffu, lm1, 1));
        lm1 = fmaxf(lm1, __shfl_xor_sync(0xffffffffu, lm1, 2));
        float mn0 = fmaxf(m0r, lm0), mn1 = fmaxf(m1r, lm1);
        float al0 = fexp2(m0r - mn0), al1 = fexp2(m1r - mn1);
        m0r = mn0; m1r = mn1;
        l0r *= al0; l1r *= al1;
#pragma unroll
        for (int n=0;n<8;n++){
            Oa[n][0] *= al0; Oa[n][1] *= al0;
            Oa[n][2] *= al1; Oa[n][3] *= al1;
        }

        float s0 = 0.f, s1 = 0.f;
#pragma unroll
        for (int j=0;j<8;j++){
            S[j][0] = fexp2(S[j][0] - mn0);
            S[j][1] = fexp2(S[j][1] - mn0);
            S[j][2] = fexp2(S[j][2] - mn1);
            S[j][3] = fexp2(S[j][3] - mn1);
            s0 += S[j][0] + S[j][1];
            s1 += S[j][2] + S[j][3];
        }
        s0 += __shfl_xor_sync(0xffffffffu, s0, 1);
        s0 += __shfl_xor_sync(0xffffffffu, s0, 2);
        s1 += __shfl_xor_sync(0xffffffffu, s1, 1);
        s1 += __shfl_xor_sync(0xffffffffu, s1, 2);
        l0r += s0; l1r += s1;

        // ---- P single fp16 (accumulator layout == A-operand layout) ----
        uint32_t ps[4][4];
#pragma unroll
        for (int t=0;t<4;t++){
            ps[t][0] = pack2h_single(S[2*t][0],   S[2*t][1]);
            ps[t][1] = pack2h_single(S[2*t][2],   S[2*t][3]);
            ps[t][2] = pack2h_single(S[2*t+1][0], S[2*t+1][1]);
            ps[t][3] = pack2h_single(S[2*t+1][2], S[2*t+1][3]);
        }

        // ---- O += P V (1 mma per n8 block) ----
#pragma unroll
        for (int t=0;t<4;t++){
#pragma unroll
            for (int np=0;np<4;np++){
                uint32_t vh4[4];
                uint32_t a = (uint32_t)((t*16 + vrow_base)*FSD + np*16 + vcol_base);
                ldsm4t(vh4, smem_u32(Vhs + a));
                mma16816h(Oa[2*np],   ps[t], vh4);
                mma16816h(Oa[2*np+1], ps[t], vh4+2);
            }
        }
    }

    // ---- normalize + split-store O (bf16 hi/lo for output GEMM) ----
    float inv0 = 1.0f / l0r, inv1 = 1.0f / l1r;
    size_t row0 = qrow0 + w*16 + (L>>2);
    size_t row1 = row0 + 8;
    int colb = h*64 + 2*(L&3);
#pragma unroll
    for (int n=0;n<8;n++){
        uint32_t lo, hi;
        hi = pack2(Oa[n][0]*inv0, Oa[n][1]*inv0, lo);
        *(uint32_t*)(Th + row0*Dc + colb + n*8) = hi;
        *(uint32_t*)(Tl + row0*Dc + colb + n*8) = lo;
        hi = pack2(Oa[n][2]*inv1, Oa[n][3]*inv1, lo);
        *(uint32_t*)(Th + row1*Dc + colb + n*8) = hi;
        *(uint32_t*)(Tl + row1*Dc + colb + n*8) = lo;
    }
}

// ---------------------------------------------------------------------------
extern "C" void kernel_launch(void* const* d_in, const int* in_sizes, int n_in,
                              void* d_out, int out_size)
{
    const float* x  = (const float*)d_in[0];
    const float* Wq = (const float*)d_in[1];
    const float* bq = (const float*)d_in[2];
    const float* Wk = (const float*)d_in[3];
    const float* bk = (const float*)d_in[4];
    const float* Wv = (const float*)d_in[5];
    const float* bv = (const float*)d_in[6];
    const float* Wo = (const float*)d_in[7];
    const float* bo = (const float*)d_in[8];
    float* out = (float*)d_out;

    __nv_bfloat16 *xh, *xl, *Wh, *Wl, *Tph, *Tpl;
    __half *Qh, *Ql, *Kh, *Kl, *Vh;
    cudaGetSymbolAddress((void**)&xh, g_xh);  cudaGetSymbolAddress((void**)&xl, g_xl);
    cudaGetSymbolAddress((void**)&Wh, g_Wh);  cudaGetSymbolAddress((void**)&Wl, g_Wl);
    cudaGetSymbolAddress((void**)&Qh, g_Qh);  cudaGetSymbolAddress((void**)&Ql, g_Ql);
    cudaGetSymbolAddress((void**)&Kh, g_Kh);  cudaGetSymbolAddress((void**)&Kl, g_Kl);
    cudaGetSymbolAddress((void**)&Vh, g_Vh);
    cudaGetSymbolAddress((void**)&Tph, g_Th); cudaGetSymbolAddress((void**)&Tpl, g_Tl);

    cudaFuncSetAttribute(gemm_proj, cudaFuncAttributeMaxDynamicSharedMemorySize, G_SMEM);
    cudaFuncSetAttribute(gemm_out,  cudaFuncAttributeMaxDynamicSharedMemorySize, G_SMEM);
    cudaFuncSetAttribute(flash_kernel, cudaFuncAttributeMaxDynamicSharedMemorySize, FL_SMEM);

    // ---- pre-split x and weights (bf16, 2 launches) ----
    split_x_kernel<<<(NR*Dc/4)/256, 256>>>(x, xh, xl);
    split_w_kernel<<<4*(DD/4)/256, 256>>>(Wq, Wv, Wk, Wo, Wh, Wl);

    // ---- merged projections + fused bias/rope/fp16 epilogue ----
    gemm_proj<<<dim3(24, NR/128), 256, G_SMEM>>>(xh, xl, Wh, Wl,
                                                 bq, bv, bk,
                                                 Qh, Ql, Kh, Kl, Vh);

    // ---- single-pass flash attention (fp16 operands) ----
    flash_kernel<<<dim3(Lc/128, Bc*16), 256, FL_SMEM>>>(Qh, Ql, Kh, Kl, Vh,
                                                        Tph, Tpl);

    // ---- output projection + fused bias ----
    gemm_out<<<dim3(Dc/128, NR/128), 256, G_SMEM>>>(Tph, Tpl, Wh + 3*(size_t)DD,
                                                    Wl + 3*(size_t)DD, bo, out);
}

// round 17
// speedup vs baseline: 6.2475x; 1.2209x over previous
#include <cuda_runtime.h>
#include <cuda_bf16.h>
#include <cuda_fp16.h>
#include <mma.h>
#include <math.h>
#include <stdint.h>

using namespace nvcuda;

#define Bc 2
#define Lc 2048
#define Dc 1024
#define NR (Bc*Lc)
#define DD (Dc*Dc)

// bf16 split operands (Q/K projection inputs)
__device__ __nv_bfloat16 g_xh[NR*Dc], g_xl[NR*Dc];
__device__ __nv_bfloat16 g_Wh[2*DD],  g_Wl[2*DD];     // slots: 0=Wq, 1=Wv(->K)
// fp16 single operands (V projection + output projection)
__device__ __half g_xs[NR*Dc];
__device__ __half g_Wks[DD];                           // Wk (-> V path)
__device__ __half g_Wos[DD];
// fp16 flash operands
__device__ __half g_Qh[NR*Dc], g_Ql[NR*Dc];
__device__ __half g_Kh[NR*Dc], g_Kl[NR*Dc];
__device__ __half g_Vh[NR*Dc];
// flash output (single fp16, feeds out-GEMM)
__device__ __half g_Ts[NR*Dc];

// ---------------------------------------------------------------------------
// helpers
// ---------------------------------------------------------------------------
__device__ __forceinline__ uint32_t smem_u32(const void* p){
    uint32_t a;
    asm("{ .reg .u64 t; cvta.to.shared.u64 t, %1; cvt.u32.u64 %0, t; }"
        : "=r"(a) : "l"(p));
    return a;
}
__device__ __forceinline__ float fexp2(float x){
    float y; asm("ex2.approx.f32 %0, %1;" : "=f"(y) : "f"(x)); return y;
}
__device__ __forceinline__ uint32_t pack2(float a, float b, uint32_t& lo){
    __nv_bfloat16 ha = __float2bfloat16(a), hb = __float2bfloat16(b);
    __nv_bfloat16 la = __float2bfloat16(a - __bfloat162float(ha));
    __nv_bfloat16 lb = __float2bfloat16(b - __bfloat162float(hb));
    lo = (uint32_t)__bfloat16_as_ushort(la) | ((uint32_t)__bfloat16_as_ushort(lb)<<16);
    return (uint32_t)__bfloat16_as_ushort(ha) | ((uint32_t)__bfloat16_as_ushort(hb)<<16);
}
__device__ __forceinline__ void store_split4(void* ph, void* pl, float4 v){
    uint2 H, L;
    H.x = pack2(v.x, v.y, L.x);
    H.y = pack2(v.z, v.w, L.y);
    *(uint2*)ph = H;
    *(uint2*)pl = L;
}
__device__ __forceinline__ uint32_t pack2h(float a, float b, uint32_t& lo){
    __half ha = __float2half(a), hb = __float2half(b);
    __half la = __float2half(a - __half2float(ha));
    __half lb = __float2half(b - __half2float(hb));
    lo = (uint32_t)__half_as_ushort(la) | ((uint32_t)__half_as_ushort(lb)<<16);
    return (uint32_t)__half_as_ushort(ha) | ((uint32_t)__half_as_ushort(hb)<<16);
}
__device__ __forceinline__ uint32_t pack2h_single(float a, float b){
    __half ha = __float2half(a), hb = __float2half(b);
    return (uint32_t)__half_as_ushort(ha) | ((uint32_t)__half_as_ushort(hb)<<16);
}
__device__ __forceinline__ void cpasync16(uint32_t saddr, const void* g){
    asm volatile("cp.async.ca.shared.global [%0], [%1], 16;" :: "r"(saddr), "l"(g));
}
#define CP_COMMIT() asm volatile("cp.async.commit_group;" ::: "memory")
#define CP_WAIT1()  asm volatile("cp.async.wait_group 1;" ::: "memory")
#define CP_WAIT0()  asm volatile("cp.async.wait_group 0;" ::: "memory")

__device__ __forceinline__ void mma16816h(float* d, const uint32_t* a, const uint32_t* b){
    asm volatile(
        "mma.sync.aligned.m16n8k16.row.col.f32.f16.f16.f32 "
        "{%0,%1,%2,%3}, {%4,%5,%6,%7}, {%8,%9}, {%0,%1,%2,%3};"
        : "+f"(d[0]), "+f"(d[1]), "+f"(d[2]), "+f"(d[3])
        : "r"(a[0]), "r"(a[1]), "r"(a[2]), "r"(a[3]), "r"(b[0]), "r"(b[1]));
}
__device__ __forceinline__ void ldsm4(uint32_t* r, uint32_t addr){
    asm volatile("ldmatrix.sync.aligned.m8n8.x4.shared.b16 {%0,%1,%2,%3}, [%4];"
        : "=r"(r[0]), "=r"(r[1]), "=r"(r[2]), "=r"(r[3]) : "r"(addr));
}
__device__ __forceinline__ void ldsm4t(uint32_t* r, uint32_t addr){
    asm volatile("ldmatrix.sync.aligned.m8n8.x4.trans.shared.b16 {%0,%1,%2,%3}, [%4];"
        : "=r"(r[0]), "=r"(r[1]), "=r"(r[2]), "=r"(r[3]) : "r"(addr));
}

typedef wmma::fragment<wmma::matrix_a,16,16,16,__nv_bfloat16,wmma::row_major> AFrag;
typedef wmma::fragment<wmma::matrix_b,16,16,16,__nv_bfloat16,wmma::col_major> BFragC;
typedef wmma::fragment<wmma::matrix_a,16,16,16,__half,wmma::row_major> AFragH;
typedef wmma::fragment<wmma::matrix_b,16,16,16,__half,wmma::col_major> BFragHC;
typedef wmma::fragment<wmma::accumulator,16,16,16,float> CFrag;

// ---------------------------------------------------------------------------
// split kernels
// ---------------------------------------------------------------------------
__global__ __launch_bounds__(256) void split_x_kernel(
    const float* __restrict__ in, __nv_bfloat16* __restrict__ hi,
    __nv_bfloat16* __restrict__ lo, __half* __restrict__ xs)
{
    int i = blockIdx.x*256 + threadIdx.x;
    float4 v = ((const float4*)in)[i];
    store_split4(hi + 4*(size_t)i, lo + 4*(size_t)i, v);
    uint2 s;
    s.x = pack2h_single(v.x, v.y);
    s.y = pack2h_single(v.z, v.w);
    *(uint2*)(xs + 4*(size_t)i) = s;
}
// slots: 0=Wq (bf16 split), 1=Wv->K (bf16 split), 2=Wk->V (fp16), 3=Wo (fp16)
__global__ __launch_bounds__(256) void split_w_kernel(
    const float* __restrict__ Wq, const float* __restrict__ Wv,
    const float* __restrict__ Wk, const float* __restrict__ Wo,
    __nv_bfloat16* __restrict__ hi, __nv_bfloat16* __restrict__ lo,
    __half* __restrict__ Wks, __half* __restrict__ Wos)
{
    int slot = blockIdx.x >> 10;
    const float* src = slot==0 ? Wq : slot==1 ? Wv : slot==2 ? Wk : Wo;
    int i = (blockIdx.x & 1023)*256 + threadIdx.x;
    float4 v = ((const float4*)src)[i];
    if (slot < 2){
        size_t o = (size_t)slot*DD + 4*(size_t)i;
        store_split4(hi + o, lo + o, v);
    } else {
        __half* dst = (slot==2) ? Wks : Wos;
        uint2 s;
        s.x = pack2h_single(v.x, v.y);
        s.y = pack2h_single(v.z, v.w);
        *(uint2*)(dst + 4*(size_t)i) = s;
    }
}

// ---------------------------------------------------------------------------
// bf16 3-mma GEMM core (Q/K projections), cp.async double-buffered, K-chunk 32
// ---------------------------------------------------------------------------
#define GS 40
#define GMAT (128*GS)
#define G_SMEM (2*4*GMAT*2)       // 81920 bytes

__device__ __forceinline__ void gemm_core(
    const __nv_bfloat16* __restrict__ Agh, const __nv_bfloat16* __restrict__ Agl,
    const __nv_bfloat16* __restrict__ Bgh, const __nv_bfloat16* __restrict__ Bgl,
    __nv_bfloat16* sm, uint32_t sbase, int tid, int wm, int wn,
    int m0, int n0, CFrag (&acc)[2][4])
{
#define G_LOAD(k0, bsel) do { \
    uint32_t s0 = sbase + (uint32_t)((bsel)*4*GMAT)*2; \
    _Pragma("unroll") \
    for (int i=0;i<2;i++){ \
        int g = tid + i*256; \
        int r = g>>2, c8 = g&3; \
        uint32_t so = s0 + (uint32_t)(r*GS + c8*8)*2; \
        size_t ga = (size_t)(m0+r)*Dc + (k0) + c8*8; \
        size_t gb = (size_t)(n0+r)*Dc + (k0) + c8*8; \
        cpasync16(so,              Agh + ga); \
        cpasync16(so + 2*GMAT,     Agl + ga); \
        cpasync16(so + 4*GMAT,     Bgh + gb); \
        cpasync16(so + 6*GMAT,     Bgl + gb); \
    } } while(0)

    G_LOAD(0, 0);
    CP_COMMIT();

    for (int ch=0; ch<32; ch++){
        if (ch < 31){ G_LOAD((ch+1)*32, (ch+1)&1); CP_COMMIT(); CP_WAIT1(); }
        else CP_WAIT0();
        __syncthreads();

        const __nv_bfloat16* Ah = sm + (ch&1)*4*GMAT;
        const __nv_bfloat16* Al = Ah + GMAT;
        const __nv_bfloat16* Bh = Ah + 2*GMAT;
        const __nv_bfloat16* Bl = Ah + 3*GMAT;
#pragma unroll
        for (int st=0; st<2; st++){
            AFrag ah[2], al[2];
#pragma unroll
            for (int im=0;im<2;im++){
                wmma::load_matrix_sync(ah[im], Ah + (wm*32+im*16)*GS + st*16, GS);
                wmma::load_matrix_sync(al[im], Al + (wm*32+im*16)*GS + st*16, GS);
            }
#pragma unroll
            for (int in=0;in<4;in++){
                BFragC bh_, bl_;
                wmma::load_matrix_sync(bh_, Bh + (wn*64+in*16)*GS + st*16, GS);
                wmma::load_matrix_sync(bl_, Bl + (wn*64+in*16)*GS + st*16, GS);
#pragma unroll
                for (int im=0;im<2;im++){
                    wmma::mma_sync(acc[im][in], ah[im], bh_, acc[im][in]);
                    wmma::mma_sync(acc[im][in], ah[im], bl_, acc[im][in]);
                    wmma::mma_sync(acc[im][in], al[im], bh_, acc[im][in]);
                }
            }
        }
        __syncthreads();
    }
#undef G_LOAD
}

// ---------------------------------------------------------------------------
// Q/K projection GEMM: grid (16, 32). slot = blockIdx.x>>3 (0=Q, 1=K).
// Epilogue: bias + xPos rotary + fp16 hi/lo split.
// ---------------------------------------------------------------------------
#define STS 132

__global__ __launch_bounds__(256, 2) void gemm_proj(
    const __nv_bfloat16* __restrict__ Agh, const __nv_bfloat16* __restrict__ Agl,
    const __nv_bfloat16* __restrict__ Wh,  const __nv_bfloat16* __restrict__ Wl,
    const float* __restrict__ bq, const float* __restrict__ bv,
    __half* __restrict__ Qh, __half* __restrict__ Ql,
    __half* __restrict__ Kh, __half* __restrict__ Kl)
{
    extern __shared__ __nv_bfloat16 sm[];
    uint32_t sbase = smem_u32(sm);
    const int tid = threadIdx.x, wid = tid>>5;
    const int wm = wid>>1, wn = wid&1;
    const int slot = blockIdx.x>>3;
    const int m0 = blockIdx.y*128, n0 = (blockIdx.x&7)*128;

    CFrag acc[2][4];
#pragma unroll
    for (int i=0;i<2;i++)
#pragma unroll
      for (int j=0;j<4;j++) wmma::fill_fragment(acc[i][j], 0.0f);

    gemm_core(Agh, Agl, Wh + (size_t)slot*DD, Wl + (size_t)slot*DD,
              sm, sbase, tid, wm, wn, m0, n0, acc);

    float* stf = (float*)sm;
#pragma unroll
    for (int im=0;im<2;im++)
#pragma unroll
      for (int in=0;in<4;in++)
        wmma::store_matrix_sync(&stf[(wm*32+im*16)*STS + wn*64+in*16],
                                acc[im][in], STS, wmma::mem_row_major);
    __syncthreads();

    const float* bias = slot==0 ? bq : bv;
#pragma unroll
    for (int i=0;i<32;i++){
        int idx = tid + i*256;
        int r = idx>>6, cp = idx&63;
        int cc = n0 + 2*cp;
        float a  = stf[r*STS + 2*cp]     + bias[cc];
        float b2 = stf[r*STS + 2*cp + 1] + bias[cc+1];
        size_t base = (size_t)(m0 + r)*Dc + cc;
        int m = m0 + r, l = m & (Lc-1), j = cc & 63;
        float jf = (float)j;
        float inv_freq = powf(10000.0f, -jf * (1.0f/64.0f));
        float fr = (float)l * inv_freq;
        float sn, cs; sincosf(fr, &sn, &cs);
        float sv = (jf + 25.6f) * (1.0f/89.6f);
        float pw = ((float)l - 1024.0f) * (1.0f/512.0f);
        float sc = powf(sv, pw);
        float s = (slot==0) ? sc * (0.03125f * 1.4426950408889634f)
                            : 1.0f/sc;
        float o0 = (a*cs - b2*sn) * s;
        float o1 = (b2*cs + a*sn) * s;
        uint32_t lo, hi = pack2h(o0, o1, lo);
        __half* Dh = (slot==0) ? Qh : Kh;
        __half* Dl = (slot==0) ? Ql : Kl;
        *(uint32_t*)(Dh + base) = hi;
        *(uint32_t*)(Dl + base) = lo;
    }
}

// ---------------------------------------------------------------------------
// fp16 single x single GEMM (V projection / output projection), 1 mma,
// K-chunk 64, cp.async double-buffered.
//   MODE 0: V = A@B^T + bias -> fp16 single (Vh)
//   MODE 1: out = A@B^T + bias -> f32
// ---------------------------------------------------------------------------
#define GS2 72
#define GMAT2 (128*GS2)               // 9216 elems
#define G2_SMEM (2*2*GMAT2*2)         // 73728 bytes

template<int MODE>
__global__ __launch_bounds__(256, 2) void gemm_half(
    const __half* __restrict__ Ag, const __half* __restrict__ Bg,
    const float* __restrict__ bias, float* __restrict__ outf,
    __half* __restrict__ outh)
{
    extern __shared__ __half sm2[];
    uint32_t sbase = smem_u32(sm2);
    const int tid = threadIdx.x, wid = tid>>5;
    const int wm = wid>>1, wn = wid&1;
    const int m0 = blockIdx.y*128, n0 = blockIdx.x*128;

    CFrag acc[2][4];
#pragma unroll
    for (int i=0;i<2;i++)
#pragma unroll
      for (int j=0;j<4;j++) wmma::fill_fragment(acc[i][j], 0.0f);

#define G2_LOAD(k0, bsel) do { \
    uint32_t s0 = sbase + (uint32_t)((bsel)*2*GMAT2)*2; \
    _Pragma("unroll") \
    for (int i=0;i<4;i++){ \
        int g = tid + i*256; \
        int r = g>>3, c8 = g&7; \
        uint32_t so = s0 + (uint32_t)(r*GS2 + c8*8)*2; \
        cpasync16(so,            Ag + (size_t)(m0+r)*Dc + (k0) + c8*8); \
        cpasync16(so + 2*GMAT2,  Bg + (size_t)(n0+r)*Dc + (k0) + c8*8); \
    } } while(0)

    G2_LOAD(0, 0);
    CP_COMMIT();

    for (int ch=0; ch<16; ch++){
        if (ch < 15){ G2_LOAD((ch+1)*64, (ch+1)&1); CP_COMMIT(); CP_WAIT1(); }
        else CP_WAIT0();
        __syncthreads();

        const __half* Ah = sm2 + (ch&1)*2*GMAT2;
        const __half* Bh = Ah + GMAT2;
#pragma unroll
        for (int st=0; st<4; st++){
            AFragH a_[2];
#pragma unroll
            for (int im=0;im<2;im++)
                wmma::load_matrix_sync(a_[im], Ah + (wm*32+im*16)*GS2 + st*16, GS2);
#pragma unroll
            for (int in=0;in<4;in++){
                BFragHC b_;
                wmma::load_matrix_sync(b_, Bh + (wn*64+in*16)*GS2 + st*16, GS2);
#pragma unroll
                for (int im=0;im<2;im++)
                    wmma::mma_sync(acc[im][in], a_[im], b_, acc[im][in]);
            }
        }
        __syncthreads();
    }
#undef G2_LOAD

    float* stf = (float*)sm2;
#pragma unroll
    for (int im=0;im<2;im++)
#pragma unroll
      for (int in=0;in<4;in++)
        wmma::store_matrix_sync(&stf[(wm*32+im*16)*STS + wn*64+in*16],
                                acc[im][in], STS, wmma::mem_row_major);
    __syncthreads();

    if (MODE == 0){
#pragma unroll
        for (int i=0;i<32;i++){
            int idx = tid + i*256;
            int r = idx>>6, cp = idx&63;
            int cc = n0 + 2*cp;
            float a  = stf[r*STS + 2*cp]     + bias[cc];
            float b2 = stf[r*STS + 2*cp + 1] + bias[cc+1];
            *(uint32_t*)(outh + (size_t)(m0+r)*Dc + cc) = pack2h_single(a, b2);
        }
    } else {
#pragma unroll
        for (int i=0;i<16;i++){
            int idx = tid + i*256;
            int r = idx>>5, c4 = (idx&31)<<2;
            float4 v;
            v.x = stf[r*STS + c4]     + bias[n0+c4];
            v.y = stf[r*STS + c4 + 1] + bias[n0+c4+1];
            v.z = stf[r*STS + c4 + 2] + bias[n0+c4+2];
            v.w = stf[r*STS + c4 + 3] + bias[n0+c4+3];
            *(float4*)&outf[(size_t)(m0+r)*Dc + n0 + c4] = v;
        }
    }
}

// ---------------------------------------------------------------------------
// Single-pass FA2 (unchanged core):
//   S = (Qh+Ql)·Kh + Qh·Kl  (3 mma/n8)   O += Ps·Vs (1 mma/n8)
// + warp-vote skip of O-rescale when running max unchanged.
// Output: single fp16 Ts.
// ---------------------------------------------------------------------------
#define FSD 72
#define FSLICE (64*FSD)
#define FBUF (3*FSLICE)
#define NSTAGE 3
#define FL_SMEM (NSTAGE*FBUF*2)   // 82944 bytes

__global__ __launch_bounds__(256, 2) void flash_kernel(
    const __half* __restrict__ Qhg, const __half* __restrict__ Qlg,
    const __half* __restrict__ Khg, const __half* __restrict__ Klg,
    const __half* __restrict__ Vhg, __half* __restrict__ Ts)
{
    extern __shared__ __half smf[];
    uint32_t sbase = smem_u32(smf);

    const int tid = threadIdx.x;
    const int w = tid>>5, L = tid&31;
    const int lr = L&7;
    const int qt = blockIdx.x, bh = blockIdx.y;
    const int b = bh>>4, h = bh&15;
    const size_t qrow0 = (size_t)b*Lc + qt*128;
    const size_t krow0 = (size_t)b*Lc;

    // ---- stage Q (128x64, hi+lo fp16) via cp.async ----
#pragma unroll
    for (int i=0;i<8;i++){
        int sl = i>>2;
        int gg = tid + (i&3)*256;
        int r = gg>>3, c8 = gg&7;
        const __half* src = sl ? Qlg : Qhg;
        uint32_t so = sbase + (uint32_t)(sl*128*FSD + r*FSD + c8*8)*2;
        cpasync16(so, src + (qrow0 + r)*Dc + h*64 + c8*8);
    }
    CP_COMMIT(); CP_WAIT0();
    __syncthreads();

    // ---- Q fragments to registers ----
    uint32_t qh[4][4], ql[4][4];
    {
        int g = L>>3;
        int qrow = w*16 + (g&1)*8 + lr;
        int qcol = (g>>1)*8;
#pragma unroll
        for (int kk=0;kk<4;kk++){
            ldsm4(qh[kk], smem_u32(smf + qrow*FSD + kk*16 + qcol));
            ldsm4(ql[kk], smem_u32(smf + 128*FSD + qrow*FSD + kk*16 + qcol));
        }
    }
    __syncthreads();

    float Oa[8][4];
#pragma unroll
    for (int n=0;n<8;n++){ Oa[n][0]=0.f; Oa[n][1]=0.f; Oa[n][2]=0.f; Oa[n][3]=0.f; }
    float m0r = -1e30f, m1r = -1e30f, l0r = 0.f, l1r = 0.f;

    const uint32_t krow_base = ((L>>4)<<3) + lr;
    const uint32_t kcol_base = ((L>>3)&1)<<3;
    const uint32_t vrow_base = (((L>>3)&1)<<3) + lr;
    const uint32_t vcol_base = (L>>4)<<3;

#define KV_LOAD(kt_, bsel) do { \
    _Pragma("unroll") \
    for (int i=0;i<6;i++){ \
        int sl = i>>1; \
        int gg = tid + (i&1)*256; \
        int r = gg>>3, c8 = gg&7; \
        const __half* src = (sl==0)?Khg:(sl==1)?Klg:Vhg; \
        uint32_t so = sbase + (uint32_t)((bsel)*FBUF + sl*FSLICE + r*FSD + c8*8)*2; \
        cpasync16(so, src + (krow0 + (kt_)*64 + r)*Dc + h*64 + c8*8); \
    } } while(0)

    KV_LOAD(0, 0); CP_COMMIT();
    KV_LOAD(1, 1); CP_COMMIT();

    const int NT = Lc/64;
    for (int kt=0; kt<NT; kt++){
        if (kt+2 < NT) CP_WAIT1(); else CP_WAIT0();
        __syncthreads();
        if (kt+2 < NT){ KV_LOAD(kt+2, (kt+2)%NSTAGE); CP_COMMIT(); }

        const __half* Khs = smf + (kt%NSTAGE)*FBUF;
        const __half* Kls = Khs + FSLICE;
        const __half* Vhs = Khs + 2*FSLICE;

        // ---- S = (Qh+Ql)Kh + Qh·Kl ----
        float S[8][4];
#pragma unroll
        for (int j=0;j<8;j++){ S[j][0]=0.f; S[j][1]=0.f; S[j][2]=0.f; S[j][3]=0.f; }
#pragma unroll
        for (int kk=0;kk<4;kk++){
#pragma unroll
            for (int jp=0;jp<4;jp++){
                uint32_t kh4[4], kl4[4];
                uint32_t a = (uint32_t)((jp*16 + krow_base)*FSD + kk*16 + kcol_base);
                ldsm4(kh4, smem_u32(Khs + a));
                ldsm4(kl4, smem_u32(Kls + a));
                mma16816h(S[2*jp],   qh[kk], kh4);
                mma16816h(S[2*jp],   ql[kk], kh4);
                mma16816h(S[2*jp],   qh[kk], kl4);
                mma16816h(S[2*jp+1], qh[kk], kh4+2);
                mma16816h(S[2*jp+1], ql[kk], kh4+2);
                mma16816h(S[2*jp+1], qh[kk], kl4+2);
            }
        }

        // ---- online softmax (exp2 domain) ----
        float lm0 = -1e30f, lm1 = -1e30f;
#pragma unroll
        for (int j=0;j<8;j++){
            lm0 = fmaxf(lm0, fmaxf(S[j][0], S[j][1]));
            lm1 = fmaxf(lm1, fmaxf(S[j][2], S[j][3]));
        }
        lm0 = fmaxf(lm0, __shfl_xor_sync(0xffffffffu, lm0, 1));
        lm0 = fmaxf(lm0, __shfl_xor_sync(0xffffffffu, lm0, 2));
        lm1 = fmaxf(lm1, __shfl_xor_sync(0xffffffffu, lm1, 1));
        lm1 = fmaxf(lm1, __shfl_xor_sync(0xffffffffu, lm1, 2));
        float mn0 = fmaxf(m0r, lm0), mn1 = fmaxf(m1r, lm1);
        bool changed = (mn0 != m0r) || (mn1 != m1r);
        if (__any_sync(0xffffffffu, changed)){
            float al0 = fexp2(m0r - mn0), al1 = fexp2(m1r - mn1);
            l0r *= al0; l1r *= al1;
#pragma unroll
            for (int n=0;n<8;n++){
                Oa[n][0] *= al0; Oa[n][1] *= al0;
                Oa[n][2] *= al1; Oa[n][3] *= al1;
            }
        }
        m0r = mn0; m1r = mn1;

        float s0 = 0.f, s1 = 0.f;
#pragma unroll
        for (int j=0;j<8;j++){
            S[j][0] = fexp2(S[j][0] - mn0);
            S[j][1] = fexp2(S[j][1] - mn0);
            S[j][2] = fexp2(S[j][2] - mn1);
            S[j][3] = fexp2(S[j][3] - mn1);
            s0 += S[j][0] + S[j][1];
            s1 += S[j][2] + S[j][3];
        }
        s0 += __shfl_xor_sync(0xffffffffu, s0, 1);
        s0 += __shfl_xor_sync(0xffffffffu, s0, 2);
        s1 += __shfl_xor_sync(0xffffffffu, s1, 1);
        s1 += __shfl_xor_sync(0xffffffffu, s1, 2);
        l0r += s0; l1r += s1;

        // ---- P single fp16 ----
        uint32_t ps[4][4];
#pragma unroll
        for (int t=0;t<4;t++){
            ps[t][0] = pack2h_single(S[2*t][0],   S[2*t][1]);
            ps[t][1] = pack2h_single(S[2*t][2],   S[2*t][3]);
            ps[t][2] = pack2h_single(S[2*t+1][0], S[2*t+1][1]);
            ps[t][3] = pack2h_single(S[2*t+1][2], S[2*t+1][3]);
        }

        // ---- O += P V ----
#pragma unroll
        for (int t=0;t<4;t++){
#pragma unroll
            for (int np=0;np<4;np++){
                uint32_t vh4[4];
                uint32_t a = (uint32_t)((t*16 + vrow_base)*FSD + np*16 + vcol_base);
                ldsm4t(vh4, smem_u32(Vhs + a));
                mma16816h(Oa[2*np],   ps[t], vh4);
                mma16816h(Oa[2*np+1], ps[t], vh4+2);
            }
        }
    }

    // ---- normalize + store O as single fp16 ----
    float inv0 = 1.0f / l0r, inv1 = 1.0f / l1r;
    size_t row0 = qrow0 + w*16 + (L>>2);
    size_t row1 = row0 + 8;
    int colb = h*64 + 2*(L&3);
#pragma unroll
    for (int n=0;n<8;n++){
        *(uint32_t*)(Ts + row0*Dc + colb + n*8) =
            pack2h_single(Oa[n][0]*inv0, Oa[n][1]*inv0);
        *(uint32_t*)(Ts + row1*Dc + colb + n*8) =
            pack2h_single(Oa[n][2]*inv1, Oa[n][3]*inv1);
    }
}

// ---------------------------------------------------------------------------
extern "C" void kernel_launch(void* const* d_in, const int* in_sizes, int n_in,
                              void* d_out, int out_size)
{
    const float* x  = (const float*)d_in[0];
    const float* Wq = (const float*)d_in[1];
    const float* bq = (const float*)d_in[2];
    const float* Wk = (const float*)d_in[3];
    const float* bk = (const float*)d_in[4];
    const float* Wv = (const float*)d_in[5];
    const float* bv = (const float*)d_in[6];
    const float* Wo = (const float*)d_in[7];
    const float* bo = (const float*)d_in[8];
    float* out = (float*)d_out;

    __nv_bfloat16 *xh, *xl, *Wh, *Wl;
    __half *xs, *Wks, *Wos, *Qh, *Ql, *Kh, *Kl, *Vh, *Ts;
    cudaGetSymbolAddress((void**)&xh, g_xh);   cudaGetSymbolAddress((void**)&xl, g_xl);
    cudaGetSymbolAddress((void**)&Wh, g_Wh);   cudaGetSymbolAddress((void**)&Wl, g_Wl);
    cudaGetSymbolAddress((void**)&xs, g_xs);
    cudaGetSymbolAddress((void**)&Wks, g_Wks); cudaGetSymbolAddress((void**)&Wos, g_Wos);
    cudaGetSymbolAddress((void**)&Qh, g_Qh);   cudaGetSymbolAddress((void**)&Ql, g_Ql);
    cudaGetSymbolAddress((void**)&Kh, g_Kh);   cudaGetSymbolAddress((void**)&Kl, g_Kl);
    cudaGetSymbolAddress((void**)&Vh, g_Vh);
    cudaGetSymbolAddress((void**)&Ts, g_Ts);

    cudaFuncSetAttribute(gemm_proj, cudaFuncAttributeMaxDynamicSharedMemorySize, G_SMEM);
    cudaFuncSetAttribute(gemm_half<0>, cudaFuncAttributeMaxDynamicSharedMemorySize, G2_SMEM);
    cudaFuncSetAttribute(gemm_half<1>, cudaFuncAttributeMaxDynamicSharedMemorySize, G2_SMEM);
    cudaFuncSetAttribute(flash_kernel, cudaFuncAttributeMaxDynamicSharedMemorySize, FL_SMEM);

    // ---- pre-split x and weights ----
    split_x_kernel<<<(NR*Dc/4)/256, 256>>>(x, xh, xl, xs);
    split_w_kernel<<<4*(DD/4)/256, 256>>>(Wq, Wv, Wk, Wo, Wh, Wl, Wks, Wos);

    // ---- Q/K projections (bf16 3-mma) + fused bias/rope/fp16 epilogue ----
    gemm_proj<<<dim3(16, NR/128), 256, G_SMEM>>>(xh, xl, Wh, Wl,
                                                 bq, bv, Qh, Ql, Kh, Kl);

    // ---- V projection (fp16 single, 1-mma): V = x@Wk^T + bk ----
    gemm_half<0><<<dim3(Dc/128, NR/128), 256, G2_SMEM>>>(xs, Wks, bk, nullptr, Vh);

    // ---- single-pass flash attention ----
    flash_kernel<<<dim3(Lc/128, Bc*16), 256, FL_SMEM>>>(Qh, Ql, Kh, Kl, Vh, Ts);

    // ---- output projection (fp16 single, 1-mma) + fused bias ----
    gemm_half<1><<<dim3(Dc/128, NR/128), 256, G2_SMEM>>>(Ts, Wos, bo, out, nullptr);
}